// round 1
// baseline (speedup 1.0000x reference)
#include <cuda_runtime.h>
#include <math.h>

#define BB   4
#define SQ   4096
#define SKK  1024
#define HIDN 640
#define SATD 768
#define NH   10
#define HD   64

// ---------------- scratch (device globals; no allocation allowed) ----------------
__device__ float g_SN[BB * SKK * SATD];
__device__ float g_Q [BB * SQ  * HIDN];
__device__ float g_K [BB * SKK * HIDN];
__device__ float g_V [BB * SKK * HIDN];
__device__ float g_T1[BB * SQ  * HIDN];
__device__ float g_GC[BB * SQ  * HIDN];
__device__ float g_gate[BB * SQ];
__device__ float g_loss[2];

// ---------------- LayerNorm over SATD=768 (one row per block, 256 thr) ----------------
__global__ void ln_kernel(const float* __restrict__ x, const float* __restrict__ gam,
                          const float* __restrict__ bet, float* __restrict__ y)
{
    int row = blockIdx.x;
    const float* xr = x + (size_t)row * SATD;
    float* yr = y + (size_t)row * SATD;
    int tid = threadIdx.x;
    float v[3];
    float s = 0.f, ss = 0.f;
#pragma unroll
    for (int t = 0; t < 3; t++) {
        v[t] = xr[tid + t * 256];
        s += v[t]; ss += v[t] * v[t];
    }
#pragma unroll
    for (int o = 16; o > 0; o >>= 1) {
        s  += __shfl_xor_sync(0xffffffffu, s,  o);
        ss += __shfl_xor_sync(0xffffffffu, ss, o);
    }
    __shared__ float sw[8], ssw[8];
    int w = tid >> 5, lane = tid & 31;
    if (lane == 0) { sw[w] = s; ssw[w] = ss; }
    __syncthreads();
    s = 0.f; ss = 0.f;
#pragma unroll
    for (int i = 0; i < 8; i++) { s += sw[i]; ss += ssw[i]; }
    float mean = s * (1.0f / SATD);
    float var  = ss * (1.0f / SATD) - mean * mean;
    float rstd = rsqrtf(var + 1e-5f);
#pragma unroll
    for (int t = 0; t < 3; t++) {
        int i = tid + t * 256;
        yr[i] = (v[t] - mean) * rstd * gam[i] + bet[i];
    }
}

// ---------------- SGEMM: C[M,N] = A[M,K] @ W[K,N] + bias (+ addend) ----------------
// BM=128 BN=64 BK=16, 256 threads, 8x4 microtile. M%128==0, N%64==0, K%16==0.
__global__ void __launch_bounds__(256) sgemm_kernel(
    const float* __restrict__ A, const float* __restrict__ W,
    const float* __restrict__ bias, const float* __restrict__ add,
    float* __restrict__ C, int M, int N, int K, int fuse_add)
{
    __shared__ float As[16][128];
    __shared__ float Ws[16][64];
    int tid = threadIdx.x;
    int tx = tid & 15, ty = tid >> 4;
    int m0 = blockIdx.y * 128, n0 = blockIdx.x * 64;
    float acc[8][4];
#pragma unroll
    for (int i = 0; i < 8; i++)
#pragma unroll
        for (int j = 0; j < 4; j++) acc[i][j] = 0.f;

    for (int k0 = 0; k0 < K; k0 += 16) {
#pragma unroll
        for (int t = 0; t < 2; t++) {
            int task = tid + t * 256;       // 512 float4 tasks: 128 rows x 4 k-quads
            int r = task >> 2, kq = task & 3;
            float4 a = *(const float4*)&A[(size_t)(m0 + r) * K + k0 + kq * 4];
            As[kq * 4 + 0][r] = a.x;
            As[kq * 4 + 1][r] = a.y;
            As[kq * 4 + 2][r] = a.z;
            As[kq * 4 + 3][r] = a.w;
        }
        {
            int k = tid >> 4, nq = tid & 15;
            *(float4*)&Ws[k][nq * 4] = *(const float4*)&W[(size_t)(k0 + k) * N + n0 + nq * 4];
        }
        __syncthreads();
#pragma unroll
        for (int k = 0; k < 16; k++) {
            float4 a0 = *(float4*)&As[k][ty * 8];
            float4 a1 = *(float4*)&As[k][ty * 8 + 4];
            float4 wv = *(float4*)&Ws[k][tx * 4];
            float av[8] = {a0.x, a0.y, a0.z, a0.w, a1.x, a1.y, a1.z, a1.w};
            float wa[4] = {wv.x, wv.y, wv.z, wv.w};
#pragma unroll
            for (int i = 0; i < 8; i++)
#pragma unroll
                for (int j = 0; j < 4; j++)
                    acc[i][j] = fmaf(av[i], wa[j], acc[i][j]);
        }
        __syncthreads();
    }
    float4 bv = *(const float4*)&bias[n0 + tx * 4];
#pragma unroll
    for (int i = 0; i < 8; i++) {
        size_t idx = (size_t)(m0 + ty * 8 + i) * N + n0 + tx * 4;
        float4 o;
        o.x = acc[i][0] + bv.x; o.y = acc[i][1] + bv.y;
        o.z = acc[i][2] + bv.z; o.w = acc[i][3] + bv.w;
        if (fuse_add) {
            float4 ad = *(const float4*)&add[idx];
            o.x += ad.x; o.y += ad.y; o.z += ad.z; o.w += ad.w;
        }
        *(float4*)&C[idx] = o;
    }
}

// ---------------- RoPE (in-place) on [rows, HIDN] with xy[rows,2] ----------------
// Per row: 10 heads x 32 rotation pairs = 320 threads.
__global__ void rope_kernel(float* __restrict__ t, const float* __restrict__ xy)
{
    int row = blockIdx.x;
    int tid = threadIdx.x;          // 0..319
    int head = tid >> 5;
    int j = tid & 31;
    int jj = j & 15;
    float inv = powf(10000.0f, -(float)jj * (1.0f / 16.0f));
    float coord = xy[(size_t)row * 2 + (j >> 4)];
    float ang = coord * inv;        // GEO_RATIO = 1
    float sn, cs;
    sincosf(ang, &sn, &cs);
    float* p = t + (size_t)row * HIDN + head * HD;
    float v1 = p[j];
    float v2 = p[j + 32];
    p[j]      = v1 * cs - v2 * sn;
    p[j + 32] = v1 * sn + v2 * cs;
}

// ---------------- plucker MLP stage 1: T1 = silu(P @ Wp1 + bp1) ----------------
__global__ void plucker_kernel(const float* __restrict__ P, const float* __restrict__ Wp1,
                               const float* __restrict__ bp1, float* __restrict__ T1)
{
    int row = blockIdx.x;
    __shared__ float p[6];
    if (threadIdx.x < 6) p[threadIdx.x] = P[(size_t)row * 6 + threadIdx.x];
    __syncthreads();
    for (int n = threadIdx.x; n < HIDN; n += blockDim.x) {
        float a = bp1[n];
#pragma unroll
        for (int k = 0; k < 6; k++) a = fmaf(p[k], Wp1[k * HIDN + n], a);
        T1[(size_t)row * HIDN + n] = a / (1.0f + __expf(-a));   // silu
    }
}

// ---------------- gate: sigmoid(LN(gctx) @ Wg + bg), + loss accumulation ----------------
__global__ void gate_kernel(const float* __restrict__ gc, const float* __restrict__ gam,
                            const float* __restrict__ bet, const float* __restrict__ Wg,
                            const float* __restrict__ bg, const float* __restrict__ vmask,
                            float* __restrict__ gate, float* __restrict__ lossacc)
{
    int row = blockIdx.x;
    const float* xr = gc + (size_t)row * HIDN;
    int tid = threadIdx.x;
    __shared__ float xs[HIDN];
    __shared__ float sw[8], ssw[8];
    float s = 0.f, ss = 0.f;
    for (int i = tid; i < HIDN; i += 256) {
        float v = xr[i]; xs[i] = v; s += v; ss += v * v;
    }
#pragma unroll
    for (int o = 16; o > 0; o >>= 1) {
        s  += __shfl_xor_sync(0xffffffffu, s,  o);
        ss += __shfl_xor_sync(0xffffffffu, ss, o);
    }
    int w = tid >> 5, lane = tid & 31;
    if (lane == 0) { sw[w] = s; ssw[w] = ss; }
    __syncthreads();
    s = 0.f; ss = 0.f;
#pragma unroll
    for (int i = 0; i < 8; i++) { s += sw[i]; ss += ssw[i]; }
    float mean = s * (1.0f / HIDN);
    float rstd = rsqrtf(ss * (1.0f / HIDN) - mean * mean + 1e-5f);
    float t = 0.f;
    for (int i = tid; i < HIDN; i += 256)
        t += ((xs[i] - mean) * rstd * gam[i] + bet[i]) * Wg[i];
#pragma unroll
    for (int o = 16; o > 0; o >>= 1) t += __shfl_xor_sync(0xffffffffu, t, o);
    __syncthreads();            // done reading sw before reuse
    if (lane == 0) sw[w] = t;
    __syncthreads();
    if (tid == 0) {
        float tt = 0.f;
#pragma unroll
        for (int i = 0; i < 8; i++) tt += sw[i];
        float gv = 1.0f / (1.0f + __expf(-(tt + bg[0])));
        gate[row] = gv;
        if (vmask[row] <= 0.5f) {
            atomicAdd(&lossacc[0], gv);
            atomicAdd(&lossacc[1], 1.0f);
        }
    }
}

// ---------------- flash attention: 64q x 64k tiles, online softmax ----------------
// grid (SQ/64, NH, BB), 256 threads (16x16), 4x4 microtile, smem 48KB (Ks reused for P).
__global__ void __launch_bounds__(256) attn_kernel(
    const float* __restrict__ Q, const float* __restrict__ K,
    const float* __restrict__ V, const float* __restrict__ gate,
    const float* __restrict__ vmask, float* __restrict__ out)
{
    __shared__ float Qs[64 * 64];   // [d][q], xor-swizzled quads
    __shared__ float Ks[64 * 64];   // [d][k] swizzled; later reused as P [q][k] plain
    __shared__ float Vs[64 * 64];   // [k][d] plain
    int tid = threadIdx.x;
    int tx = tid & 15, ty = tid >> 4;
    int b = blockIdx.z, h = blockIdx.y, q0 = blockIdx.x * 64;

    const float* Qb = Q + ((size_t)(b * SQ + q0)) * HIDN + h * HD;
#pragma unroll
    for (int t = 0; t < 4; t++) {
        int task = tid + t * 256;           // 1024 float4 tasks: 64 q x 16 d-quads
        int q = task >> 4, dq = task & 15;
        float4 a = *(const float4*)(Qb + (size_t)q * HIDN + dq * 4);
        int c = (((q >> 2) ^ dq) << 2) + (q & 3);
        Qs[(dq * 4 + 0) * 64 + c] = a.x;
        Qs[(dq * 4 + 1) * 64 + c] = a.y;
        Qs[(dq * 4 + 2) * 64 + c] = a.z;
        Qs[(dq * 4 + 3) * 64 + c] = a.w;
    }

    float m_run[4], l_run[4], acc[4][4];
#pragma unroll
    for (int i = 0; i < 4; i++) {
        m_run[i] = -1e30f; l_run[i] = 0.f;
#pragma unroll
        for (int j = 0; j < 4; j++) acc[i][j] = 0.f;
    }

    for (int kb = 0; kb < SKK; kb += 64) {
        const float* Kb = K + ((size_t)(b * SKK + kb)) * HIDN + h * HD;
        const float* Vb = V + ((size_t)(b * SKK + kb)) * HIDN + h * HD;
        __syncthreads();    // prev-iter readers of Ks/Vs done (also orders Qs fill, iter 0)
#pragma unroll
        for (int t = 0; t < 4; t++) {
            int task = tid + t * 256;
            int k = task >> 4, dq = task & 15;
            float4 a = *(const float4*)(Kb + (size_t)k * HIDN + dq * 4);
            int c = (((k >> 2) ^ dq) << 2) + (k & 3);
            Ks[(dq * 4 + 0) * 64 + c] = a.x;
            Ks[(dq * 4 + 1) * 64 + c] = a.y;
            Ks[(dq * 4 + 2) * 64 + c] = a.z;
            Ks[(dq * 4 + 3) * 64 + c] = a.w;
            *(float4*)&Vs[k * 64 + dq * 4] = *(const float4*)(Vb + (size_t)k * HIDN + dq * 4);
        }
        __syncthreads();

        float s[4][4];
#pragma unroll
        for (int i = 0; i < 4; i++)
#pragma unroll
            for (int j = 0; j < 4; j++) s[i][j] = 0.f;
#pragma unroll 16
        for (int d = 0; d < 64; d++) {
            int d2 = d >> 2;
            float4 qv = *(float4*)&Qs[d * 64 + ((ty ^ d2) << 2)];
            float4 kv = *(float4*)&Ks[d * 64 + ((tx ^ d2) << 2)];
            float qa[4] = {qv.x, qv.y, qv.z, qv.w};
            float ka[4] = {kv.x, kv.y, kv.z, kv.w};
#pragma unroll
            for (int i = 0; i < 4; i++)
#pragma unroll
                for (int j = 0; j < 4; j++)
                    s[i][j] = fmaf(qa[i], ka[j], s[i][j]);
        }

        // online softmax update (row groups = 16 lanes within warp)
#pragma unroll
        for (int i = 0; i < 4; i++) {
            float m = -1e30f;
#pragma unroll
            for (int j = 0; j < 4; j++) { s[i][j] *= 0.125f; m = fmaxf(m, s[i][j]); }
#pragma unroll
            for (int o = 8; o > 0; o >>= 1) m = fmaxf(m, __shfl_xor_sync(0xffffffffu, m, o));
            float mn = fmaxf(m_run[i], m);
            float alpha = __expf(m_run[i] - mn);
            m_run[i] = mn;
            float rs = 0.f;
#pragma unroll
            for (int j = 0; j < 4; j++) { s[i][j] = __expf(s[i][j] - mn); rs += s[i][j]; }
#pragma unroll
            for (int o = 8; o > 0; o >>= 1) rs += __shfl_xor_sync(0xffffffffu, rs, o);
            l_run[i] = l_run[i] * alpha + rs;
#pragma unroll
            for (int j = 0; j < 4; j++) acc[i][j] *= alpha;
        }
        __syncthreads();    // all done reading Ks before overwriting with P
#pragma unroll
        for (int i = 0; i < 4; i++)
            *(float4*)&Ks[(ty * 4 + i) * 64 + tx * 4] =
                make_float4(s[i][0], s[i][1], s[i][2], s[i][3]);
        __syncthreads();

        // O += P @ V
#pragma unroll
        for (int k0 = 0; k0 < 64; k0 += 4) {
            float p[4][4];
#pragma unroll
            for (int i = 0; i < 4; i++) {
                float4 t4 = *(float4*)&Ks[(ty * 4 + i) * 64 + k0];
                p[i][0] = t4.x; p[i][1] = t4.y; p[i][2] = t4.z; p[i][3] = t4.w;
            }
#pragma unroll
            for (int kk = 0; kk < 4; kk++) {
                float4 v4 = *(float4*)&Vs[(k0 + kk) * 64 + tx * 4];
#pragma unroll
                for (int i = 0; i < 4; i++) {
                    acc[i][0] = fmaf(p[i][kk], v4.x, acc[i][0]);
                    acc[i][1] = fmaf(p[i][kk], v4.y, acc[i][1]);
                    acc[i][2] = fmaf(p[i][kk], v4.z, acc[i][2]);
                    acc[i][3] = fmaf(p[i][kk], v4.w, acc[i][3]);
                }
            }
        }
    }

    // epilogue: normalize, gate, mask, write
#pragma unroll
    for (int i = 0; i < 4; i++) {
        int q = q0 + ty * 4 + i;
        size_t ridx = (size_t)b * SQ + q;
        float gmul = gate[ridx] * (vmask[ridx] > 0.5f ? 1.0f : 0.0f);
        float inv = gmul / l_run[i];
        float4 o = make_float4(acc[i][0] * inv, acc[i][1] * inv,
                               acc[i][2] * inv, acc[i][3] * inv);
        *(float4*)(out + ridx * HIDN + h * HD + tx * 4) = o;
    }
}

__global__ void zero_loss_kernel(float* l) { l[0] = 0.f; l[1] = 0.f; }
__global__ void loss_final_kernel(const float* l, float* o)
{
    o[0] = l[0] / fmaxf(l[1], 1.0f) * 0.05f;
}

// ---------------- launch ----------------
extern "C" void kernel_launch(void* const* d_in, const int* in_sizes, int n_in,
                              void* d_out, int out_size)
{
    (void)in_sizes; (void)n_in;
    const float* hidden = (const float*)d_in[0];
    const float* sat    = (const float*)d_in[1];
    const float* sat_xy = (const float*)d_in[2];
    const float* bev_xy = (const float*)d_in[3];
    const float* plk    = (const float*)d_in[4];
    const float* vmask  = (const float*)d_in[5];
    const float* Wq  = (const float*)d_in[6];
    const float* bq  = (const float*)d_in[7];
    const float* lng = (const float*)d_in[8];
    const float* lnb = (const float*)d_in[9];
    const float* Wk  = (const float*)d_in[10];
    const float* bk  = (const float*)d_in[11];
    const float* Wv  = (const float*)d_in[12];
    const float* bv  = (const float*)d_in[13];
    const float* Wp1 = (const float*)d_in[14];
    const float* bp1 = (const float*)d_in[15];
    const float* Wp2 = (const float*)d_in[16];
    const float* bp2 = (const float*)d_in[17];
    const float* gg  = (const float*)d_in[18];
    const float* gb  = (const float*)d_in[19];
    const float* Wg  = (const float*)d_in[20];
    const float* bg  = (const float*)d_in[21];
    float* out = (float*)d_out;

    float *pSN, *pQ, *pK, *pV, *pT1, *pGC, *pGate, *pLoss;
    cudaGetSymbolAddress((void**)&pSN,   g_SN);
    cudaGetSymbolAddress((void**)&pQ,    g_Q);
    cudaGetSymbolAddress((void**)&pK,    g_K);
    cudaGetSymbolAddress((void**)&pV,    g_V);
    cudaGetSymbolAddress((void**)&pT1,   g_T1);
    cudaGetSymbolAddress((void**)&pGC,   g_GC);
    cudaGetSymbolAddress((void**)&pGate, g_gate);
    cudaGetSymbolAddress((void**)&pLoss, g_loss);

    zero_loss_kernel<<<1, 1>>>(pLoss);
    ln_kernel<<<BB * SKK, 256>>>(sat, lng, lnb, pSN);

    dim3 gq(HIDN / 64, (BB * SQ) / 128);
    dim3 gk(HIDN / 64, (BB * SKK) / 128);
    sgemm_kernel<<<gq, 256>>>(hidden, Wq, bq, nullptr, pQ, BB * SQ,  HIDN, HIDN, 0);
    sgemm_kernel<<<gk, 256>>>(pSN,    Wk, bk, nullptr, pK, BB * SKK, HIDN, SATD, 0);
    sgemm_kernel<<<gk, 256>>>(pSN,    Wv, bv, nullptr, pV, BB * SKK, HIDN, SATD, 0);

    rope_kernel<<<BB * SQ,  320>>>(pQ, bev_xy);
    rope_kernel<<<BB * SKK, 320>>>(pK, sat_xy);

    plucker_kernel<<<BB * SQ, 256>>>(plk, Wp1, bp1, pT1);
    sgemm_kernel<<<gq, 256>>>(pT1, Wp2, bp2, hidden, pGC, BB * SQ, HIDN, HIDN, 1);

    gate_kernel<<<BB * SQ, 256>>>(pGC, gg, gb, Wg, bg, vmask, pGate, pLoss);

    dim3 ga(SQ / 64, NH, BB);
    attn_kernel<<<ga, 256>>>(pQ, pK, pV, pGate, vmask, out);

    loss_final_kernel<<<1, 1>>>(pLoss, out + (out_size - 1));
}

// round 2
// speedup vs baseline: 2.2049x; 2.2049x over previous
#include <cuda_runtime.h>
#include <math.h>

#define BB   4
#define SQ   4096
#define SKK  1024
#define HIDN 640
#define SATD 768
#define NH   10
#define HD   64

// ---------------- scratch (device globals; no allocation allowed) ----------------
__device__ float g_SN[BB * SKK * SATD];
__device__ float g_Q [BB * SQ  * HIDN];
__device__ float g_K [BB * SKK * HIDN];
__device__ float g_V [BB * SKK * HIDN];
__device__ float g_T1[BB * SQ  * HIDN];
__device__ float g_GC[BB * SQ  * HIDN];
__device__ float g_gate[BB * SQ];
__device__ float g_loss[2];

// ---------------- tf32 helpers ----------------
__device__ __forceinline__ unsigned f2tf(float f) {
    unsigned u;
    asm("cvt.rna.tf32.f32 %0, %1;" : "=r"(u) : "f"(f));
    return u;
}
__device__ __forceinline__ float rtf(float f) {       // round-to-tf32, keep as float
    unsigned u;
    asm("cvt.rna.tf32.f32 %0, %1;" : "=r"(u) : "f"(f));
    return __uint_as_float(u);
}
__device__ __forceinline__ void mma_tf32(float c[4],
                                         unsigned a0, unsigned a1, unsigned a2, unsigned a3,
                                         unsigned b0, unsigned b1)
{
    asm volatile("mma.sync.aligned.m16n8k8.row.col.f32.tf32.tf32.f32 "
                 "{%0,%1,%2,%3}, {%4,%5,%6,%7}, {%8,%9}, {%0,%1,%2,%3};"
                 : "+f"(c[0]), "+f"(c[1]), "+f"(c[2]), "+f"(c[3])
                 : "r"(a0), "r"(a1), "r"(a2), "r"(a3), "r"(b0), "r"(b1));
}

// ---------------- LayerNorm over SATD=768 (one row per block, 256 thr) ----------------
__global__ void ln_kernel(const float* __restrict__ x, const float* __restrict__ gam,
                          const float* __restrict__ bet, float* __restrict__ y)
{
    int row = blockIdx.x;
    const float* xr = x + (size_t)row * SATD;
    float* yr = y + (size_t)row * SATD;
    int tid = threadIdx.x;
    float v[3];
    float s = 0.f, ss = 0.f;
#pragma unroll
    for (int t = 0; t < 3; t++) {
        v[t] = xr[tid + t * 256];
        s += v[t]; ss += v[t] * v[t];
    }
#pragma unroll
    for (int o = 16; o > 0; o >>= 1) {
        s  += __shfl_xor_sync(0xffffffffu, s,  o);
        ss += __shfl_xor_sync(0xffffffffu, ss, o);
    }
    __shared__ float sw[8], ssw[8];
    int w = tid >> 5, lane = tid & 31;
    if (lane == 0) { sw[w] = s; ssw[w] = ss; }
    __syncthreads();
    s = 0.f; ss = 0.f;
#pragma unroll
    for (int i = 0; i < 8; i++) { s += sw[i]; ss += ssw[i]; }
    float mean = s * (1.0f / SATD);
    float var  = ss * (1.0f / SATD) - mean * mean;
    float rstd = rsqrtf(var + 1e-5f);
#pragma unroll
    for (int t = 0; t < 3; t++) {
        int i = tid + t * 256;
        yr[i] = (v[t] - mean) * rstd * gam[i] + bet[i];
    }
}

// ---------------- TF32 GEMM: C[M,N] = A[M,K] @ W[K,N] + bias (+ add) ----------------
// BM=128 BN=128 BK=16, 256 threads (8 warps as 2x4), warptile 64x32, mma m16n8k8.
__global__ void __launch_bounds__(256) gemm_tf32_kernel(
    const float* __restrict__ A, const float* __restrict__ W,
    const float* __restrict__ bias, const float* __restrict__ add,
    float* __restrict__ C, int M, int N, int K, int fuse_add)
{
    __shared__ unsigned As[16][136];   // [k][m^((k>>2)<<3)]  (conflict-free frag ld/st)
    __shared__ unsigned Bs[16][136];   // [k][n]
    int tid = threadIdx.x;
    int lane = tid & 31, wid = tid >> 5;
    int g = lane >> 2, tg = lane & 3;
    int wm = wid >> 2, wn = wid & 3;
    int m0 = blockIdx.y * 128, n0 = blockIdx.x * 128;

    float4 apre[2], bpre[2];
    // initial tile load (k0 = 0)
#pragma unroll
    for (int t = 0; t < 2; t++) {
        int task = tid + t * 256;
        int r = task >> 2, kq = task & 3;
        apre[t] = *(const float4*)&A[(size_t)(m0 + r) * K + kq * 4];
    }
#pragma unroll
    for (int t = 0; t < 2; t++) {
        int task = tid + t * 256;
        int k = task >> 5, nq = task & 31;
        bpre[t] = *(const float4*)&W[(size_t)k * N + n0 + nq * 4];
    }
    // store tile 0
#pragma unroll
    for (int t = 0; t < 2; t++) {
        int task = tid + t * 256;
        int r = task >> 2, kq = task & 3;
        int mp = r ^ (kq << 3);
        As[kq * 4 + 0][mp] = f2tf(apre[t].x);
        As[kq * 4 + 1][mp] = f2tf(apre[t].y);
        As[kq * 4 + 2][mp] = f2tf(apre[t].z);
        As[kq * 4 + 3][mp] = f2tf(apre[t].w);
    }
#pragma unroll
    for (int t = 0; t < 2; t++) {
        int task = tid + t * 256;
        int k = task >> 5, nq = task & 31;
        uint4 u = make_uint4(f2tf(bpre[t].x), f2tf(bpre[t].y), f2tf(bpre[t].z), f2tf(bpre[t].w));
        *(uint4*)&Bs[k][nq * 4] = u;
    }
    __syncthreads();

    float acc[4][4][4];
#pragma unroll
    for (int i = 0; i < 4; i++)
#pragma unroll
        for (int j = 0; j < 4; j++)
#pragma unroll
            for (int q = 0; q < 4; q++) acc[i][j][q] = 0.f;

    for (int k0 = 0; k0 < K; k0 += 16) {
        int more = (k0 + 16 < K);
        if (more) {
#pragma unroll
            for (int t = 0; t < 2; t++) {
                int task = tid + t * 256;
                int r = task >> 2, kq = task & 3;
                apre[t] = *(const float4*)&A[(size_t)(m0 + r) * K + k0 + 16 + kq * 4];
            }
#pragma unroll
            for (int t = 0; t < 2; t++) {
                int task = tid + t * 256;
                int k = task >> 5, nq = task & 31;
                bpre[t] = *(const float4*)&W[(size_t)(k0 + 16 + k) * N + n0 + nq * 4];
            }
        }
#pragma unroll
        for (int ks = 0; ks < 16; ks += 8) {
            int s0 = ks * 2;          // ((ks  )>>2)<<3
            int s1 = ks * 2 + 8;      // ((ks+4)>>2)<<3
            unsigned af[4][4], bf[4][2];
#pragma unroll
            for (int i = 0; i < 4; i++) {
                int m = wm * 64 + i * 16 + g;
                af[i][0] = As[ks + tg][m ^ s0];
                af[i][1] = As[ks + tg][(m + 8) ^ s0];
                af[i][2] = As[ks + 4 + tg][m ^ s1];
                af[i][3] = As[ks + 4 + tg][(m + 8) ^ s1];
            }
#pragma unroll
            for (int j = 0; j < 4; j++) {
                int n = wn * 32 + j * 8 + g;
                bf[j][0] = Bs[ks + tg][n];
                bf[j][1] = Bs[ks + 4 + tg][n];
            }
#pragma unroll
            for (int i = 0; i < 4; i++)
#pragma unroll
                for (int j = 0; j < 4; j++)
                    mma_tf32(acc[i][j], af[i][0], af[i][1], af[i][2], af[i][3],
                             bf[j][0], bf[j][1]);
        }
        __syncthreads();
        if (more) {
#pragma unroll
            for (int t = 0; t < 2; t++) {
                int task = tid + t * 256;
                int r = task >> 2, kq = task & 3;
                int mp = r ^ (kq << 3);
                As[kq * 4 + 0][mp] = f2tf(apre[t].x);
                As[kq * 4 + 1][mp] = f2tf(apre[t].y);
                As[kq * 4 + 2][mp] = f2tf(apre[t].z);
                As[kq * 4 + 3][mp] = f2tf(apre[t].w);
            }
#pragma unroll
            for (int t = 0; t < 2; t++) {
                int task = tid + t * 256;
                int k = task >> 5, nq = task & 31;
                uint4 u = make_uint4(f2tf(bpre[t].x), f2tf(bpre[t].y), f2tf(bpre[t].z), f2tf(bpre[t].w));
                *(uint4*)&Bs[k][nq * 4] = u;
            }
        }
        __syncthreads();
    }

    // epilogue
#pragma unroll
    for (int i = 0; i < 4; i++) {
        int r0 = m0 + wm * 64 + i * 16 + g;
#pragma unroll
        for (int j = 0; j < 4; j++) {
            int c = n0 + wn * 32 + j * 8 + 2 * tg;
            float2 bv = *(const float2*)&bias[c];
            size_t i0 = (size_t)r0 * N + c;
            size_t i1 = (size_t)(r0 + 8) * N + c;
            float2 o0 = make_float2(acc[i][j][0] + bv.x, acc[i][j][1] + bv.y);
            float2 o1 = make_float2(acc[i][j][2] + bv.x, acc[i][j][3] + bv.y);
            if (fuse_add) {
                float2 a0 = *(const float2*)&add[i0];
                float2 a1 = *(const float2*)&add[i1];
                o0.x += a0.x; o0.y += a0.y; o1.x += a1.x; o1.y += a1.y;
            }
            *(float2*)&C[i0] = o0;
            *(float2*)&C[i1] = o1;
        }
    }
}

// ---------------- RoPE (in-place) on [rows, HIDN] with xy[rows,2] ----------------
__global__ void rope_kernel(float* __restrict__ t, const float* __restrict__ xy)
{
    int row = blockIdx.x;
    int tid = threadIdx.x;          // 0..319
    int head = tid >> 5;
    int j = tid & 31;
    int jj = j & 15;
    float inv = powf(10000.0f, -(float)jj * (1.0f / 16.0f));
    float coord = xy[(size_t)row * 2 + (j >> 4)];
    float ang = coord * inv;
    float sn, cs;
    sincosf(ang, &sn, &cs);
    float* p = t + (size_t)row * HIDN + head * HD;
    float v1 = p[j];
    float v2 = p[j + 32];
    p[j]      = v1 * cs - v2 * sn;
    p[j + 32] = v1 * sn + v2 * cs;
}

// ---------------- plucker MLP stage 1: T1 = silu(P @ Wp1 + bp1) ----------------
__global__ void plucker_kernel(const float* __restrict__ P, const float* __restrict__ Wp1,
                               const float* __restrict__ bp1, float* __restrict__ T1)
{
    int row = blockIdx.x;
    __shared__ float p[6];
    if (threadIdx.x < 6) p[threadIdx.x] = P[(size_t)row * 6 + threadIdx.x];
    __syncthreads();
    for (int n = threadIdx.x; n < HIDN; n += blockDim.x) {
        float a = bp1[n];
#pragma unroll
        for (int k = 0; k < 6; k++) a = fmaf(p[k], Wp1[k * HIDN + n], a);
        T1[(size_t)row * HIDN + n] = a / (1.0f + __expf(-a));
    }
}

// ---------------- gate: sigmoid(LN(gctx) @ Wg + bg), + loss accumulation ----------------
__global__ void gate_kernel(const float* __restrict__ gc, const float* __restrict__ gam,
                            const float* __restrict__ bet, const float* __restrict__ Wg,
                            const float* __restrict__ bg, const float* __restrict__ vmask,
                            float* __restrict__ gate, float* __restrict__ lossacc)
{
    int row = blockIdx.x;
    const float* xr = gc + (size_t)row * HIDN;
    int tid = threadIdx.x;
    __shared__ float xs[HIDN];
    __shared__ float sw[8], ssw[8];
    float s = 0.f, ss = 0.f;
    for (int i = tid; i < HIDN; i += 256) {
        float v = xr[i]; xs[i] = v; s += v; ss += v * v;
    }
#pragma unroll
    for (int o = 16; o > 0; o >>= 1) {
        s  += __shfl_xor_sync(0xffffffffu, s,  o);
        ss += __shfl_xor_sync(0xffffffffu, ss, o);
    }
    int w = tid >> 5, lane = tid & 31;
    if (lane == 0) { sw[w] = s; ssw[w] = ss; }
    __syncthreads();
    s = 0.f; ss = 0.f;
#pragma unroll
    for (int i = 0; i < 8; i++) { s += sw[i]; ss += ssw[i]; }
    float mean = s * (1.0f / HIDN);
    float rstd = rsqrtf(ss * (1.0f / HIDN) - mean * mean + 1e-5f);
    float t = 0.f;
    for (int i = tid; i < HIDN; i += 256)
        t += ((xs[i] - mean) * rstd * gam[i] + bet[i]) * Wg[i];
#pragma unroll
    for (int o = 16; o > 0; o >>= 1) t += __shfl_xor_sync(0xffffffffu, t, o);
    __syncthreads();
    if (lane == 0) sw[w] = t;
    __syncthreads();
    if (tid == 0) {
        float tt = 0.f;
#pragma unroll
        for (int i = 0; i < 8; i++) tt += sw[i];
        float gv = 1.0f / (1.0f + __expf(-(tt + bg[0])));
        gate[row] = gv;
        if (vmask[row] <= 0.5f) {
            atomicAdd(&lossacc[0], gv);
            atomicAdd(&lossacc[1], 1.0f);
        }
    }
}

// ---------------- flash attention (tf32 mma): 64q x 64k tiles ----------------
// grid (SQ/64, NH, BB), 256 threads (8 warps as 2x4), dynamic smem 54016B.
__global__ void __launch_bounds__(256) attn_kernel(
    const float* __restrict__ Q, const float* __restrict__ K,
    const float* __restrict__ V, const float* __restrict__ gate,
    const float* __restrict__ vmask, float* __restrict__ out)
{
    extern __shared__ float smn[];
    float* Qs = smn;                       // [64][68]
    float* Ps = smn + 64 * 68;             // K tile (as [k][68]) then P ([q][68])
    float* Vs = smn + 2 * 64 * 68;         // [64][72]
    float* Ms = smn + 2 * 64 * 68 + 64 * 72;
    float* Ls = Ms + 64;
    float* Al = Ls + 64;

    int tid = threadIdx.x;
    int lane = tid & 31, wid = tid >> 5;
    int g = lane >> 2, tg = lane & 3;
    int wm = wid >> 2, wn = wid & 3;
    int b = blockIdx.z, h = blockIdx.y, q0 = blockIdx.x * 64;

    const float* Qg = Q + ((size_t)(b * SQ + q0)) * HIDN + h * HD;
#pragma unroll
    for (int t = 0; t < 4; t++) {
        int task = tid + t * 256;
        int q = task >> 4, dq = task & 15;
        float4 a = *(const float4*)(Qg + (size_t)q * HIDN + dq * 4);
        a.x = rtf(a.x); a.y = rtf(a.y); a.z = rtf(a.z); a.w = rtf(a.w);
        *(float4*)&Qs[q * 68 + dq * 4] = a;
    }
    if (tid < 64) { Ms[tid] = -1e30f; Ls[tid] = 0.f; }

    float acc[2][2][4];
#pragma unroll
    for (int i = 0; i < 2; i++)
#pragma unroll
        for (int j = 0; j < 2; j++)
#pragma unroll
            for (int q = 0; q < 4; q++) acc[i][j][q] = 0.f;

    for (int kb = 0; kb < SKK; kb += 64) {
        __syncthreads();   // prior readers of Ps/Vs done (iter0: Qs/Ms stores visible)
        const float* Kg = K + ((size_t)(b * SKK + kb)) * HIDN + h * HD;
        const float* Vg = V + ((size_t)(b * SKK + kb)) * HIDN + h * HD;
#pragma unroll
        for (int t = 0; t < 4; t++) {
            int task = tid + t * 256;
            int kk = task >> 4, dq = task & 15;
            float4 a = *(const float4*)(Kg + (size_t)kk * HIDN + dq * 4);
            a.x = rtf(a.x); a.y = rtf(a.y); a.z = rtf(a.z); a.w = rtf(a.w);
            *(float4*)&Ps[kk * 68 + dq * 4] = a;
            float4 v = *(const float4*)(Vg + (size_t)kk * HIDN + dq * 4);
            v.x = rtf(v.x); v.y = rtf(v.y); v.z = rtf(v.z); v.w = rtf(v.w);
            *(float4*)&Vs[kk * 72 + dq * 4] = v;
        }
        __syncthreads();

        // S = Q @ K^T (warptile 32q x 16k)
        float s[2][2][4];
#pragma unroll
        for (int i = 0; i < 2; i++)
#pragma unroll
            for (int j = 0; j < 2; j++)
#pragma unroll
                for (int q = 0; q < 4; q++) s[i][j][q] = 0.f;
#pragma unroll
        for (int d0 = 0; d0 < 64; d0 += 8) {
            unsigned qf[2][4], kf[2][2];
#pragma unroll
            for (int i = 0; i < 2; i++) {
                int q = wm * 32 + i * 16 + g;
                qf[i][0] = __float_as_uint(Qs[q * 68 + d0 + tg]);
                qf[i][1] = __float_as_uint(Qs[(q + 8) * 68 + d0 + tg]);
                qf[i][2] = __float_as_uint(Qs[q * 68 + d0 + 4 + tg]);
                qf[i][3] = __float_as_uint(Qs[(q + 8) * 68 + d0 + 4 + tg]);
            }
#pragma unroll
            for (int j = 0; j < 2; j++) {
                int kk = wn * 16 + j * 8 + g;
                kf[j][0] = __float_as_uint(Ps[kk * 68 + d0 + tg]);
                kf[j][1] = __float_as_uint(Ps[kk * 68 + d0 + 4 + tg]);
            }
#pragma unroll
            for (int i = 0; i < 2; i++)
#pragma unroll
                for (int j = 0; j < 2; j++)
                    mma_tf32(s[i][j], qf[i][0], qf[i][1], qf[i][2], qf[i][3],
                             kf[j][0], kf[j][1]);
        }
        __syncthreads();   // all warps done reading K tile from Ps

        // write scaled S into Ps as [q][k]
#pragma unroll
        for (int i = 0; i < 2; i++) {
            int q = wm * 32 + i * 16 + g;
#pragma unroll
            for (int j = 0; j < 2; j++) {
                int c = wn * 16 + j * 8 + 2 * tg;
                *(float2*)&Ps[q * 68 + c] =
                    make_float2(s[i][j][0] * 0.125f, s[i][j][1] * 0.125f);
                *(float2*)&Ps[(q + 8) * 68 + c] =
                    make_float2(s[i][j][2] * 0.125f, s[i][j][3] * 0.125f);
            }
        }
        __syncthreads();

        // online softmax: 4 threads per row
        {
            int row = tid >> 2, sub = tid & 3;
            float* pr = &Ps[row * 68 + sub * 16];
            float4 p0 = *(float4*)pr;
            float4 p1 = *(float4*)(pr + 4);
            float4 p2 = *(float4*)(pr + 8);
            float4 p3 = *(float4*)(pr + 12);
            float mx = fmaxf(fmaxf(fmaxf(p0.x, p0.y), fmaxf(p0.z, p0.w)),
                             fmaxf(fmaxf(p1.x, p1.y), fmaxf(p1.z, p1.w)));
            mx = fmaxf(mx, fmaxf(fmaxf(fmaxf(p2.x, p2.y), fmaxf(p2.z, p2.w)),
                                 fmaxf(fmaxf(p3.x, p3.y), fmaxf(p3.z, p3.w))));
            mx = fmaxf(mx, __shfl_xor_sync(0xffffffffu, mx, 1));
            mx = fmaxf(mx, __shfl_xor_sync(0xffffffffu, mx, 2));
            float mold = Ms[row];
            float mn = fmaxf(mold, mx);
            float alpha = __expf(mold - mn);
            p0.x = __expf(p0.x - mn); p0.y = __expf(p0.y - mn);
            p0.z = __expf(p0.z - mn); p0.w = __expf(p0.w - mn);
            p1.x = __expf(p1.x - mn); p1.y = __expf(p1.y - mn);
            p1.z = __expf(p1.z - mn); p1.w = __expf(p1.w - mn);
            p2.x = __expf(p2.x - mn); p2.y = __expf(p2.y - mn);
            p2.z = __expf(p2.z - mn); p2.w = __expf(p2.w - mn);
            p3.x = __expf(p3.x - mn); p3.y = __expf(p3.y - mn);
            p3.z = __expf(p3.z - mn); p3.w = __expf(p3.w - mn);
            float rs = (p0.x + p0.y + p0.z + p0.w) + (p1.x + p1.y + p1.z + p1.w)
                     + (p2.x + p2.y + p2.z + p2.w) + (p3.x + p3.y + p3.z + p3.w);
            rs += __shfl_xor_sync(0xffffffffu, rs, 1);
            rs += __shfl_xor_sync(0xffffffffu, rs, 2);
            // store tf32-rounded P
            p0.x = rtf(p0.x); p0.y = rtf(p0.y); p0.z = rtf(p0.z); p0.w = rtf(p0.w);
            p1.x = rtf(p1.x); p1.y = rtf(p1.y); p1.z = rtf(p1.z); p1.w = rtf(p1.w);
            p2.x = rtf(p2.x); p2.y = rtf(p2.y); p2.z = rtf(p2.z); p2.w = rtf(p2.w);
            p3.x = rtf(p3.x); p3.y = rtf(p3.y); p3.z = rtf(p3.z); p3.w = rtf(p3.w);
            *(float4*)pr        = p0;
            *(float4*)(pr + 4)  = p1;
            *(float4*)(pr + 8)  = p2;
            *(float4*)(pr + 12) = p3;
            if (sub == 0) {
                Ms[row] = mn;
                Ls[row] = Ls[row] * alpha + rs;
                Al[row] = alpha;
            }
        }
        __syncthreads();

        // rescale O accumulators, then O += P @ V (warptile 32q x 16d)
        float al0[2], al1[2];
#pragma unroll
        for (int i = 0; i < 2; i++) {
            al0[i] = Al[wm * 32 + i * 16 + g];
            al1[i] = Al[wm * 32 + i * 16 + g + 8];
        }
#pragma unroll
        for (int i = 0; i < 2; i++)
#pragma unroll
            for (int j = 0; j < 2; j++) {
                acc[i][j][0] *= al0[i]; acc[i][j][1] *= al0[i];
                acc[i][j][2] *= al1[i]; acc[i][j][3] *= al1[i];
            }
#pragma unroll
        for (int k0 = 0; k0 < 64; k0 += 8) {
            unsigned pf[2][4], vf[2][2];
#pragma unroll
            for (int i = 0; i < 2; i++) {
                int q = wm * 32 + i * 16 + g;
                pf[i][0] = __float_as_uint(Ps[q * 68 + k0 + tg]);
                pf[i][1] = __float_as_uint(Ps[(q + 8) * 68 + k0 + tg]);
                pf[i][2] = __float_as_uint(Ps[q * 68 + k0 + 4 + tg]);
                pf[i][3] = __float_as_uint(Ps[(q + 8) * 68 + k0 + 4 + tg]);
            }
#pragma unroll
            for (int j = 0; j < 2; j++) {
                int d = wn * 16 + j * 8 + g;
                vf[j][0] = __float_as_uint(Vs[(k0 + tg) * 72 + d]);
                vf[j][1] = __float_as_uint(Vs[(k0 + 4 + tg) * 72 + d]);
            }
#pragma unroll
            for (int i = 0; i < 2; i++)
#pragma unroll
                for (int j = 0; j < 2; j++)
                    mma_tf32(acc[i][j], pf[i][0], pf[i][1], pf[i][2], pf[i][3],
                             vf[j][0], vf[j][1]);
        }
    }

    // epilogue: normalize, gate, mask, write
#pragma unroll
    for (int i = 0; i < 2; i++) {
        int r0 = wm * 32 + i * 16 + g;
        int r1 = r0 + 8;
        size_t ridx0 = (size_t)b * SQ + q0 + r0;
        size_t ridx1 = (size_t)b * SQ + q0 + r1;
        float g0 = gate[ridx0] * (vmask[ridx0] > 0.5f ? 1.0f : 0.0f) / Ls[r0];
        float g1 = gate[ridx1] * (vmask[ridx1] > 0.5f ? 1.0f : 0.0f) / Ls[r1];
#pragma unroll
        for (int j = 0; j < 2; j++) {
            int col = h * HD + wn * 16 + j * 8 + 2 * tg;
            *(float2*)(out + ridx0 * HIDN + col) =
                make_float2(acc[i][j][0] * g0, acc[i][j][1] * g0);
            *(float2*)(out + ridx1 * HIDN + col) =
                make_float2(acc[i][j][2] * g1, acc[i][j][3] * g1);
        }
    }
}

__global__ void zero_loss_kernel(float* l) { l[0] = 0.f; l[1] = 0.f; }
__global__ void loss_final_kernel(const float* l, float* o)
{
    o[0] = l[0] / fmaxf(l[1], 1.0f) * 0.05f;
}

// ---------------- launch ----------------
extern "C" void kernel_launch(void* const* d_in, const int* in_sizes, int n_in,
                              void* d_out, int out_size)
{
    (void)in_sizes; (void)n_in;
    const float* hidden = (const float*)d_in[0];
    const float* sat    = (const float*)d_in[1];
    const float* sat_xy = (const float*)d_in[2];
    const float* bev_xy = (const float*)d_in[3];
    const float* plk    = (const float*)d_in[4];
    const float* vmask  = (const float*)d_in[5];
    const float* Wq  = (const float*)d_in[6];
    const float* bq  = (const float*)d_in[7];
    const float* lng = (const float*)d_in[8];
    const float* lnb = (const float*)d_in[9];
    const float* Wk  = (const float*)d_in[10];
    const float* bk  = (const float*)d_in[11];
    const float* Wv  = (const float*)d_in[12];
    const float* bv  = (const float*)d_in[13];
    const float* Wp1 = (const float*)d_in[14];
    const float* bp1 = (const float*)d_in[15];
    const float* Wp2 = (const float*)d_in[16];
    const float* bp2 = (const float*)d_in[17];
    const float* gg  = (const float*)d_in[18];
    const float* gb  = (const float*)d_in[19];
    const float* Wg  = (const float*)d_in[20];
    const float* bg  = (const float*)d_in[21];
    float* out = (float*)d_out;

    float *pSN, *pQ, *pK, *pV, *pT1, *pGC, *pGate, *pLoss;
    cudaGetSymbolAddress((void**)&pSN,   g_SN);
    cudaGetSymbolAddress((void**)&pQ,    g_Q);
    cudaGetSymbolAddress((void**)&pK,    g_K);
    cudaGetSymbolAddress((void**)&pV,    g_V);
    cudaGetSymbolAddress((void**)&pT1,   g_T1);
    cudaGetSymbolAddress((void**)&pGC,   g_GC);
    cudaGetSymbolAddress((void**)&pGate, g_gate);
    cudaGetSymbolAddress((void**)&pLoss, g_loss);

    static const int ATTN_SMEM = (2 * 64 * 68 + 64 * 72 + 3 * 64) * 4;
    cudaFuncSetAttribute(attn_kernel, cudaFuncAttributeMaxDynamicSharedMemorySize, ATTN_SMEM);

    zero_loss_kernel<<<1, 1>>>(pLoss);
    ln_kernel<<<BB * SKK, 256>>>(sat, lng, lnb, pSN);

    dim3 gq(HIDN / 128, (BB * SQ) / 128);
    dim3 gk(HIDN / 128, (BB * SKK) / 128);
    gemm_tf32_kernel<<<gq, 256>>>(hidden, Wq, bq, nullptr, pQ, BB * SQ,  HIDN, HIDN, 0);
    gemm_tf32_kernel<<<gk, 256>>>(pSN,    Wk, bk, nullptr, pK, BB * SKK, HIDN, SATD, 0);
    gemm_tf32_kernel<<<gk, 256>>>(pSN,    Wv, bv, nullptr, pV, BB * SKK, HIDN, SATD, 0);

    rope_kernel<<<BB * SQ,  320>>>(pQ, bev_xy);
    rope_kernel<<<BB * SKK, 320>>>(pK, sat_xy);

    plucker_kernel<<<BB * SQ, 256>>>(plk, Wp1, bp1, pT1);
    gemm_tf32_kernel<<<gq, 256>>>(pT1, Wp2, bp2, hidden, pGC, BB * SQ, HIDN, HIDN, 1);

    gate_kernel<<<BB * SQ, 256>>>(pGC, gg, gb, Wg, bg, vmask, pGate, pLoss);

    dim3 ga(SQ / 64, NH, BB);
    attn_kernel<<<ga, 256, ATTN_SMEM>>>(pQ, pK, pV, pGate, vmask, out);

    loss_final_kernel<<<1, 1>>>(pLoss, out + (out_size - 1));
}

// round 3
// speedup vs baseline: 2.2354x; 1.0138x over previous
#include <cuda_runtime.h>
#include <math.h>

#define BB   4
#define SQ   4096
#define SKK  1024
#define HIDN 640
#define SATD 768
#define NH   10
#define HD   64

// ---------------- scratch (device globals; no allocation allowed) ----------------
__device__ float g_SN[BB * SKK * SATD];
__device__ float g_Q [BB * SQ  * HIDN];
__device__ float g_K [BB * SKK * HIDN];
__device__ float g_V [BB * SKK * HIDN];
__device__ float g_T1[BB * SQ  * HIDN];
__device__ float g_GC[BB * SQ  * HIDN];
__device__ float g_gate[BB * SQ];
__device__ float g_loss[2];

// ---------------- tf32 helpers ----------------
__device__ __forceinline__ unsigned f2tf(float f) {
    unsigned u;
    asm("cvt.rna.tf32.f32 %0, %1;" : "=r"(u) : "f"(f));
    return u;
}
__device__ __forceinline__ float rtf(float f) {
    unsigned u;
    asm("cvt.rna.tf32.f32 %0, %1;" : "=r"(u) : "f"(f));
    return __uint_as_float(u);
}
__device__ __forceinline__ void mma_tf32(float c[4],
                                         unsigned a0, unsigned a1, unsigned a2, unsigned a3,
                                         unsigned b0, unsigned b1)
{
    asm volatile("mma.sync.aligned.m16n8k8.row.col.f32.tf32.tf32.f32 "
                 "{%0,%1,%2,%3}, {%4,%5,%6,%7}, {%8,%9}, {%0,%1,%2,%3};"
                 : "+f"(c[0]), "+f"(c[1]), "+f"(c[2]), "+f"(c[3])
                 : "r"(a0), "r"(a1), "r"(a2), "r"(a3), "r"(b0), "r"(b1));
}

// ---------------- LayerNorm over SATD=768 ----------------
__global__ void ln_kernel(const float* __restrict__ x, const float* __restrict__ gam,
                          const float* __restrict__ bet, float* __restrict__ y)
{
    int row = blockIdx.x;
    const float* xr = x + (size_t)row * SATD;
    float* yr = y + (size_t)row * SATD;
    int tid = threadIdx.x;
    float v[3];
    float s = 0.f, ss = 0.f;
#pragma unroll
    for (int t = 0; t < 3; t++) {
        v[t] = xr[tid + t * 256];
        s += v[t]; ss += v[t] * v[t];
    }
#pragma unroll
    for (int o = 16; o > 0; o >>= 1) {
        s  += __shfl_xor_sync(0xffffffffu, s,  o);
        ss += __shfl_xor_sync(0xffffffffu, ss, o);
    }
    __shared__ float sw[8], ssw[8];
    int w = tid >> 5, lane = tid & 31;
    if (lane == 0) { sw[w] = s; ssw[w] = ss; }
    __syncthreads();
    s = 0.f; ss = 0.f;
#pragma unroll
    for (int i = 0; i < 8; i++) { s += sw[i]; ss += ssw[i]; }
    float mean = s * (1.0f / SATD);
    float var  = ss * (1.0f / SATD) - mean * mean;
    float rstd = rsqrtf(var + 1e-5f);
#pragma unroll
    for (int t = 0; t < 3; t++) {
        int i = tid + t * 256;
        yr[i] = (v[t] - mean) * rstd * gam[i] + bet[i];
    }
}

// ---------------- TF32 GEMM: BM=128 BN=64 BK=16, double-buffered, 1 sync/iter ----
// 8 warps as 2x4, warptile 64x16.
__global__ void __launch_bounds__(256, 2) gemm_tf32_kernel(
    const float* __restrict__ A, const float* __restrict__ W,
    const float* __restrict__ bias, const float* __restrict__ add,
    float* __restrict__ C, int M, int N, int K, int fuse_add)
{
    __shared__ unsigned As[2][16][136];   // [k][m ^ ((k>>2)<<3)]
    __shared__ unsigned Bs[2][16][72];
    int tid = threadIdx.x;
    int lane = tid & 31, wid = tid >> 5;
    int g = lane >> 2, tg = lane & 3;
    int wm = wid >> 2, wn = wid & 3;     // wm 0..1, wn 0..3
    int m0 = blockIdx.y * 128, n0 = blockIdx.x * 64;

    int ar[2], akq[2];
#pragma unroll
    for (int t = 0; t < 2; t++) { int task = tid + t * 256; ar[t] = task >> 2; akq[t] = task & 3; }
    int bk = tid >> 4, bnq = tid & 15;

    float4 apre[2], bpre;
#pragma unroll
    for (int t = 0; t < 2; t++)
        apre[t] = *(const float4*)&A[(size_t)(m0 + ar[t]) * K + akq[t] * 4];
    bpre = *(const float4*)&W[(size_t)bk * N + n0 + bnq * 4];

#pragma unroll
    for (int t = 0; t < 2; t++) {
        int mp = ar[t] ^ (akq[t] << 3);
        As[0][akq[t] * 4 + 0][mp] = f2tf(apre[t].x);
        As[0][akq[t] * 4 + 1][mp] = f2tf(apre[t].y);
        As[0][akq[t] * 4 + 2][mp] = f2tf(apre[t].z);
        As[0][akq[t] * 4 + 3][mp] = f2tf(apre[t].w);
    }
    *(uint4*)&Bs[0][bk][bnq * 4] =
        make_uint4(f2tf(bpre.x), f2tf(bpre.y), f2tf(bpre.z), f2tf(bpre.w));
    __syncthreads();

    float acc[4][2][4];
#pragma unroll
    for (int i = 0; i < 4; i++)
#pragma unroll
        for (int j = 0; j < 2; j++)
#pragma unroll
            for (int q = 0; q < 4; q++) acc[i][j][q] = 0.f;

    int cur = 0;
    for (int k0 = 0; k0 < K; k0 += 16) {
        int more = (k0 + 16 < K);
        if (more) {
#pragma unroll
            for (int t = 0; t < 2; t++)
                apre[t] = *(const float4*)&A[(size_t)(m0 + ar[t]) * K + k0 + 16 + akq[t] * 4];
            bpre = *(const float4*)&W[(size_t)(k0 + 16 + bk) * N + n0 + bnq * 4];
        }
#pragma unroll
        for (int ks = 0; ks < 16; ks += 8) {
            int s0 = ks * 2, s1 = ks * 2 + 8;
            unsigned af[4][4], bf[2][2];
#pragma unroll
            for (int i = 0; i < 4; i++) {
                int m = wm * 64 + i * 16 + g;
                af[i][0] = As[cur][ks + tg][m ^ s0];
                af[i][1] = As[cur][ks + tg][(m + 8) ^ s0];
                af[i][2] = As[cur][ks + 4 + tg][m ^ s1];
                af[i][3] = As[cur][ks + 4 + tg][(m + 8) ^ s1];
            }
#pragma unroll
            for (int j = 0; j < 2; j++) {
                int n = wn * 16 + j * 8 + g;
                bf[j][0] = Bs[cur][ks + tg][n];
                bf[j][1] = Bs[cur][ks + 4 + tg][n];
            }
#pragma unroll
            for (int i = 0; i < 4; i++)
#pragma unroll
                for (int j = 0; j < 2; j++)
                    mma_tf32(acc[i][j], af[i][0], af[i][1], af[i][2], af[i][3],
                             bf[j][0], bf[j][1]);
        }
        if (more) {
            int nxt = cur ^ 1;
#pragma unroll
            for (int t = 0; t < 2; t++) {
                int mp = ar[t] ^ (akq[t] << 3);
                As[nxt][akq[t] * 4 + 0][mp] = f2tf(apre[t].x);
                As[nxt][akq[t] * 4 + 1][mp] = f2tf(apre[t].y);
                As[nxt][akq[t] * 4 + 2][mp] = f2tf(apre[t].z);
                As[nxt][akq[t] * 4 + 3][mp] = f2tf(apre[t].w);
            }
            *(uint4*)&Bs[nxt][bk][bnq * 4] =
                make_uint4(f2tf(bpre.x), f2tf(bpre.y), f2tf(bpre.z), f2tf(bpre.w));
        }
        __syncthreads();
        cur ^= 1;
    }

    // epilogue
#pragma unroll
    for (int i = 0; i < 4; i++) {
        int r0 = m0 + wm * 64 + i * 16 + g;
#pragma unroll
        for (int j = 0; j < 2; j++) {
            int c = n0 + wn * 16 + j * 8 + 2 * tg;
            float2 bv = *(const float2*)&bias[c];
            size_t i0 = (size_t)r0 * N + c;
            size_t i1 = (size_t)(r0 + 8) * N + c;
            float2 o0 = make_float2(acc[i][j][0] + bv.x, acc[i][j][1] + bv.y);
            float2 o1 = make_float2(acc[i][j][2] + bv.x, acc[i][j][3] + bv.y);
            if (fuse_add) {
                float2 a0 = *(const float2*)&add[i0];
                float2 a1 = *(const float2*)&add[i1];
                o0.x += a0.x; o0.y += a0.y; o1.x += a1.x; o1.y += a1.y;
            }
            *(float2*)&C[i0] = o0;
            *(float2*)&C[i1] = o1;
        }
    }
}

// ---------------- RoPE (in-place) ----------------
__global__ void rope_kernel(float* __restrict__ t, const float* __restrict__ xy)
{
    int row = blockIdx.x;
    int tid = threadIdx.x;          // 0..319
    int head = tid >> 5;
    int j = tid & 31;
    int jj = j & 15;
    float inv = powf(10000.0f, -(float)jj * (1.0f / 16.0f));
    float coord = xy[(size_t)row * 2 + (j >> 4)];
    float ang = coord * inv;
    float sn, cs;
    sincosf(ang, &sn, &cs);
    float* p = t + (size_t)row * HIDN + head * HD;
    float v1 = p[j];
    float v2 = p[j + 32];
    p[j]      = v1 * cs - v2 * sn;
    p[j + 32] = v1 * sn + v2 * cs;
}

// ---------------- plucker MLP stage 1 ----------------
__global__ void plucker_kernel(const float* __restrict__ P, const float* __restrict__ Wp1,
                               const float* __restrict__ bp1, float* __restrict__ T1)
{
    int row = blockIdx.x;
    __shared__ float p[6];
    if (threadIdx.x < 6) p[threadIdx.x] = P[(size_t)row * 6 + threadIdx.x];
    __syncthreads();
    for (int n = threadIdx.x; n < HIDN; n += blockDim.x) {
        float a = bp1[n];
#pragma unroll
        for (int k = 0; k < 6; k++) a = fmaf(p[k], Wp1[k * HIDN + n], a);
        T1[(size_t)row * HIDN + n] = a / (1.0f + __expf(-a));
    }
}

// ---------------- gate (vmask folded into stored gate) ----------------
__global__ void gate_kernel(const float* __restrict__ gc, const float* __restrict__ gam,
                            const float* __restrict__ bet, const float* __restrict__ Wg,
                            const float* __restrict__ bg, const float* __restrict__ vmask,
                            float* __restrict__ gate, float* __restrict__ lossacc)
{
    int row = blockIdx.x;
    const float* xr = gc + (size_t)row * HIDN;
    int tid = threadIdx.x;
    __shared__ float xs[HIDN];
    __shared__ float sw[8], ssw[8];
    float s = 0.f, ss = 0.f;
    for (int i = tid; i < HIDN; i += 256) {
        float v = xr[i]; xs[i] = v; s += v; ss += v * v;
    }
#pragma unroll
    for (int o = 16; o > 0; o >>= 1) {
        s  += __shfl_xor_sync(0xffffffffu, s,  o);
        ss += __shfl_xor_sync(0xffffffffu, ss, o);
    }
    int w = tid >> 5, lane = tid & 31;
    if (lane == 0) { sw[w] = s; ssw[w] = ss; }
    __syncthreads();
    s = 0.f; ss = 0.f;
#pragma unroll
    for (int i = 0; i < 8; i++) { s += sw[i]; ss += ssw[i]; }
    float mean = s * (1.0f / HIDN);
    float rstd = rsqrtf(ss * (1.0f / HIDN) - mean * mean + 1e-5f);
    float t = 0.f;
    for (int i = tid; i < HIDN; i += 256)
        t += ((xs[i] - mean) * rstd * gam[i] + bet[i]) * Wg[i];
#pragma unroll
    for (int o = 16; o > 0; o >>= 1) t += __shfl_xor_sync(0xffffffffu, t, o);
    __syncthreads();
    if (lane == 0) sw[w] = t;
    __syncthreads();
    if (tid == 0) {
        float tt = 0.f;
#pragma unroll
        for (int i = 0; i < 8; i++) tt += sw[i];
        float gv = 1.0f / (1.0f + __expf(-(tt + bg[0])));
        bool valid = vmask[row] > 0.5f;
        gate[row] = valid ? gv : 0.0f;
        if (!valid) {
            atomicAdd(&lossacc[0], gv);
            atomicAdd(&lossacc[1], 1.0f);
        }
    }
}

// ---------------- flash attention (tf32 mma): 128q x 64k tiles ----------------
// grid (SQ/128, NH, BB), 256 threads (8 warps as 4x2).
__global__ void __launch_bounds__(256, 1) attn_kernel(
    const float* __restrict__ Q, const float* __restrict__ K,
    const float* __restrict__ V, const float* __restrict__ gate,
    float* __restrict__ out)
{
    extern __shared__ float smn[];
    float* Qs = smn;                           // [128][68]
    float* Ks = Qs + 128 * 68;                 // [64][68]
    float* Vs = Ks + 64 * 68;                  // [64][72]
    float* Ps = Vs + 64 * 72;                  // [128][68]
    float* Ms = Ps + 128 * 68;                 // [128]
    float* Ls = Ms + 128;
    float* Al = Ls + 128;

    int tid = threadIdx.x;
    int lane = tid & 31, wid = tid >> 5;
    int g = lane >> 2, tg = lane & 3;
    int wm = wid >> 1, wn = wid & 1;           // wm 0..3 (q), wn 0..1 (k/d)
    int b = blockIdx.z, h = blockIdx.y, q0 = blockIdx.x * 128;

    const float* Qg = Q + ((size_t)(b * SQ + q0)) * HIDN + h * HD;
#pragma unroll
    for (int t = 0; t < 8; t++) {
        int task = tid + t * 256;
        int q = task >> 4, dq = task & 15;
        float4 a = *(const float4*)(Qg + (size_t)q * HIDN + dq * 4);
        a.x = rtf(a.x); a.y = rtf(a.y); a.z = rtf(a.z); a.w = rtf(a.w);
        *(float4*)&Qs[q * 68 + dq * 4] = a;
    }
    if (tid < 128) { Ms[tid] = -1e30f; Ls[tid] = 0.f; }

    float acc[2][4][4];
#pragma unroll
    for (int i = 0; i < 2; i++)
#pragma unroll
        for (int j = 0; j < 4; j++)
#pragma unroll
            for (int q = 0; q < 4; q++) acc[i][j][q] = 0.f;

    for (int kb = 0; kb < SKK; kb += 64) {
        __syncthreads();   // prev PV readers of Ps/Vs done; iter0 orders Qs/Ms
        const float* Kg = K + ((size_t)(b * SKK + kb)) * HIDN + h * HD;
        const float* Vg = V + ((size_t)(b * SKK + kb)) * HIDN + h * HD;
#pragma unroll
        for (int t = 0; t < 4; t++) {
            int task = tid + t * 256;
            int kk = task >> 4, dq = task & 15;
            float4 a = *(const float4*)(Kg + (size_t)kk * HIDN + dq * 4);
            a.x = rtf(a.x); a.y = rtf(a.y); a.z = rtf(a.z); a.w = rtf(a.w);
            *(float4*)&Ks[kk * 68 + dq * 4] = a;
            float4 v = *(const float4*)(Vg + (size_t)kk * HIDN + dq * 4);
            v.x = rtf(v.x); v.y = rtf(v.y); v.z = rtf(v.z); v.w = rtf(v.w);
            *(float4*)&Vs[kk * 72 + dq * 4] = v;
        }
        __syncthreads();

        // S = Q @ K^T : warptile 32q x 32k
        float s[2][4][4];
#pragma unroll
        for (int i = 0; i < 2; i++)
#pragma unroll
            for (int j = 0; j < 4; j++)
#pragma unroll
                for (int q = 0; q < 4; q++) s[i][j][q] = 0.f;
#pragma unroll
        for (int d0 = 0; d0 < 64; d0 += 8) {
            unsigned qf[2][4], kf[4][2];
#pragma unroll
            for (int i = 0; i < 2; i++) {
                int q = wm * 32 + i * 16 + g;
                qf[i][0] = __float_as_uint(Qs[q * 68 + d0 + tg]);
                qf[i][1] = __float_as_uint(Qs[(q + 8) * 68 + d0 + tg]);
                qf[i][2] = __float_as_uint(Qs[q * 68 + d0 + 4 + tg]);
                qf[i][3] = __float_as_uint(Qs[(q + 8) * 68 + d0 + 4 + tg]);
            }
#pragma unroll
            for (int j = 0; j < 4; j++) {
                int kk = wn * 32 + j * 8 + g;
                kf[j][0] = __float_as_uint(Ks[kk * 68 + d0 + tg]);
                kf[j][1] = __float_as_uint(Ks[kk * 68 + d0 + 4 + tg]);
            }
#pragma unroll
            for (int i = 0; i < 2; i++)
#pragma unroll
                for (int j = 0; j < 4; j++)
                    mma_tf32(s[i][j], qf[i][0], qf[i][1], qf[i][2], qf[i][3],
                             kf[j][0], kf[j][1]);
        }
        // write scaled S into Ps [q][k]
#pragma unroll
        for (int i = 0; i < 2; i++) {
            int q = wm * 32 + i * 16 + g;
#pragma unroll
            for (int j = 0; j < 4; j++) {
                int c = wn * 32 + j * 8 + 2 * tg;
                *(float2*)&Ps[q * 68 + c] =
                    make_float2(s[i][j][0] * 0.125f, s[i][j][1] * 0.125f);
                *(float2*)&Ps[(q + 8) * 68 + c] =
                    make_float2(s[i][j][2] * 0.125f, s[i][j][3] * 0.125f);
            }
        }
        __syncthreads();

        // online softmax: 2 threads per row, 32 cols each
        {
            int row = tid >> 1, sub = tid & 1;
            float* pr = &Ps[row * 68 + sub * 32];
            float mx = -1e30f;
#pragma unroll
            for (int c = 0; c < 8; c++) {
                float4 p4 = *(float4*)(pr + c * 4);
                mx = fmaxf(mx, fmaxf(fmaxf(p4.x, p4.y), fmaxf(p4.z, p4.w)));
            }
            mx = fmaxf(mx, __shfl_xor_sync(0xffffffffu, mx, 1));
            float mold = Ms[row];
            float mn = fmaxf(mold, mx);
            float alpha = __expf(mold - mn);
            float rs = 0.f;
#pragma unroll
            for (int c = 0; c < 8; c++) {
                float4 p4 = *(float4*)(pr + c * 4);
                p4.x = __expf(p4.x - mn); p4.y = __expf(p4.y - mn);
                p4.z = __expf(p4.z - mn); p4.w = __expf(p4.w - mn);
                rs += (p4.x + p4.y) + (p4.z + p4.w);
                p4.x = rtf(p4.x); p4.y = rtf(p4.y);
                p4.z = rtf(p4.z); p4.w = rtf(p4.w);
                *(float4*)(pr + c * 4) = p4;
            }
            rs += __shfl_xor_sync(0xffffffffu, rs, 1);
            if (sub == 0) {
                Ms[row] = mn;
                Ls[row] = Ls[row] * alpha + rs;
                Al[row] = alpha;
            }
        }
        __syncthreads();

        // rescale O accumulators, then O += P @ V (warptile 32q x 32d)
#pragma unroll
        for (int i = 0; i < 2; i++) {
            float a0 = Al[wm * 32 + i * 16 + g];
            float a1 = Al[wm * 32 + i * 16 + g + 8];
#pragma unroll
            for (int j = 0; j < 4; j++) {
                acc[i][j][0] *= a0; acc[i][j][1] *= a0;
                acc[i][j][2] *= a1; acc[i][j][3] *= a1;
            }
        }
#pragma unroll
        for (int k0 = 0; k0 < 64; k0 += 8) {
            unsigned pf[2][4], vf[4][2];
#pragma unroll
            for (int i = 0; i < 2; i++) {
                int q = wm * 32 + i * 16 + g;
                pf[i][0] = __float_as_uint(Ps[q * 68 + k0 + tg]);
                pf[i][1] = __float_as_uint(Ps[(q + 8) * 68 + k0 + tg]);
                pf[i][2] = __float_as_uint(Ps[q * 68 + k0 + 4 + tg]);
                pf[i][3] = __float_as_uint(Ps[(q + 8) * 68 + k0 + 4 + tg]);
            }
#pragma unroll
            for (int j = 0; j < 4; j++) {
                int d = wn * 32 + j * 8 + g;
                vf[j][0] = __float_as_uint(Vs[(k0 + tg) * 72 + d]);
                vf[j][1] = __float_as_uint(Vs[(k0 + 4 + tg) * 72 + d]);
            }
#pragma unroll
            for (int i = 0; i < 2; i++)
#pragma unroll
                for (int j = 0; j < 4; j++)
                    mma_tf32(acc[i][j], pf[i][0], pf[i][1], pf[i][2], pf[i][3],
                             vf[j][0], vf[j][1]);
        }
    }

    // epilogue: normalize, gate (mask pre-folded), write
#pragma unroll
    for (int i = 0; i < 2; i++) {
        int r0 = wm * 32 + i * 16 + g;
        int r1 = r0 + 8;
        size_t ridx0 = (size_t)b * SQ + q0 + r0;
        size_t ridx1 = (size_t)b * SQ + q0 + r1;
        float g0 = gate[ridx0] / Ls[r0];
        float g1 = gate[ridx1] / Ls[r1];
#pragma unroll
        for (int j = 0; j < 4; j++) {
            int col = h * HD + wn * 32 + j * 8 + 2 * tg;
            *(float2*)(out + ridx0 * HIDN + col) =
                make_float2(acc[i][j][0] * g0, acc[i][j][1] * g0);
            *(float2*)(out + ridx1 * HIDN + col) =
                make_float2(acc[i][j][2] * g1, acc[i][j][3] * g1);
        }
    }
}

__global__ void zero_loss_kernel(float* l) { l[0] = 0.f; l[1] = 0.f; }
__global__ void loss_final_kernel(const float* l, float* o)
{
    o[0] = l[0] / fmaxf(l[1], 1.0f) * 0.05f;
}

// ---------------- launch ----------------
extern "C" void kernel_launch(void* const* d_in, const int* in_sizes, int n_in,
                              void* d_out, int out_size)
{
    (void)in_sizes; (void)n_in;
    const float* hidden = (const float*)d_in[0];
    const float* sat    = (const float*)d_in[1];
    const float* sat_xy = (const float*)d_in[2];
    const float* bev_xy = (const float*)d_in[3];
    const float* plk    = (const float*)d_in[4];
    const float* vmask  = (const float*)d_in[5];
    const float* Wq  = (const float*)d_in[6];
    const float* bq  = (const float*)d_in[7];
    const float* lng = (const float*)d_in[8];
    const float* lnb = (const float*)d_in[9];
    const float* Wk  = (const float*)d_in[10];
    const float* bk  = (const float*)d_in[11];
    const float* Wv  = (const float*)d_in[12];
    const float* bv  = (const float*)d_in[13];
    const float* Wp1 = (const float*)d_in[14];
    const float* bp1 = (const float*)d_in[15];
    const float* Wp2 = (const float*)d_in[16];
    const float* bp2 = (const float*)d_in[17];
    const float* gg  = (const float*)d_in[18];
    const float* gb  = (const float*)d_in[19];
    const float* Wg  = (const float*)d_in[20];
    const float* bg  = (const float*)d_in[21];
    float* out = (float*)d_out;

    float *pSN, *pQ, *pK, *pV, *pT1, *pGC, *pGate, *pLoss;
    cudaGetSymbolAddress((void**)&pSN,   g_SN);
    cudaGetSymbolAddress((void**)&pQ,    g_Q);
    cudaGetSymbolAddress((void**)&pK,    g_K);
    cudaGetSymbolAddress((void**)&pV,    g_V);
    cudaGetSymbolAddress((void**)&pT1,   g_T1);
    cudaGetSymbolAddress((void**)&pGC,   g_GC);
    cudaGetSymbolAddress((void**)&pGate, g_gate);
    cudaGetSymbolAddress((void**)&pLoss, g_loss);

    // streams/events created once (handles only; no device memory)
    static cudaStream_t s1 = nullptr, s2 = nullptr, s3 = nullptr;
    static cudaEvent_t e0, eln, e1, e2, e3;
    if (!s1) {
        cudaStreamCreateWithFlags(&s1, cudaStreamNonBlocking);
        cudaStreamCreateWithFlags(&s2, cudaStreamNonBlocking);
        cudaStreamCreateWithFlags(&s3, cudaStreamNonBlocking);
        cudaEventCreateWithFlags(&e0,  cudaEventDisableTiming);
        cudaEventCreateWithFlags(&eln, cudaEventDisableTiming);
        cudaEventCreateWithFlags(&e1,  cudaEventDisableTiming);
        cudaEventCreateWithFlags(&e2,  cudaEventDisableTiming);
        cudaEventCreateWithFlags(&e3,  cudaEventDisableTiming);
    }

    static const int ATTN_SMEM = (128 * 68 + 64 * 68 + 64 * 72 + 128 * 68 + 3 * 128) * 4;
    cudaFuncSetAttribute(attn_kernel, cudaFuncAttributeMaxDynamicSharedMemorySize, ATTN_SMEM);

    dim3 gq(HIDN / 64, (BB * SQ) / 128);    // 10 x 128
    dim3 gk(HIDN / 64, (BB * SKK) / 128);   // 10 x 32

    zero_loss_kernel<<<1, 1>>>(pLoss);
    cudaEventRecord(e0, 0);
    cudaStreamWaitEvent(s1, e0, 0);
    cudaStreamWaitEvent(s2, e0, 0);

    // s1: LN -> K gemm -> rope K ; s3 forks after LN for V gemm
    ln_kernel<<<BB * SKK, 256, 0, s1>>>(sat, lng, lnb, pSN);
    cudaEventRecord(eln, s1);
    cudaStreamWaitEvent(s3, eln, 0);
    gemm_tf32_kernel<<<gk, 256, 0, s1>>>(pSN, Wk, bk, nullptr, pK, BB * SKK, HIDN, SATD, 0);
    rope_kernel<<<BB * SKK, 320, 0, s1>>>(pK, sat_xy);
    cudaEventRecord(e1, s1);
    gemm_tf32_kernel<<<gk, 256, 0, s3>>>(pSN, Wv, bv, nullptr, pV, BB * SKK, HIDN, SATD, 0);
    cudaEventRecord(e3, s3);

    // s2: plucker -> PF gemm -> gate
    plucker_kernel<<<BB * SQ, 256, 0, s2>>>(plk, Wp1, bp1, pT1);
    gemm_tf32_kernel<<<gq, 256, 0, s2>>>(pT1, Wp2, bp2, hidden, pGC, BB * SQ, HIDN, HIDN, 1);
    gate_kernel<<<BB * SQ, 256, 0, s2>>>(pGC, gg, gb, Wg, bg, vmask, pGate, pLoss);
    cudaEventRecord(e2, s2);

    // stream 0: Q gemm -> rope Q
    gemm_tf32_kernel<<<gq, 256>>>(hidden, Wq, bq, nullptr, pQ, BB * SQ, HIDN, HIDN, 0);
    rope_kernel<<<BB * SQ, 320>>>(pQ, bev_xy);

    cudaStreamWaitEvent(0, e1, 0);
    cudaStreamWaitEvent(0, e3, 0);
    cudaStreamWaitEvent(0, e2, 0);

    dim3 ga(SQ / 128, NH, BB);
    attn_kernel<<<ga, 256, ATTN_SMEM>>>(pQ, pK, pV, pGate, out);

    loss_final_kernel<<<1, 1>>>(pLoss, out + (out_size - 1));
}

// round 4
// speedup vs baseline: 2.7270x; 1.2199x over previous
#include <cuda_runtime.h>
#include <math.h>

#define BB   4
#define SQ   4096
#define SKK  1024
#define HIDN 640
#define SATD 768
#define NH   10
#define HD   64

// ---------------- scratch (device globals; no allocation allowed) ----------------
__device__ float g_SN[BB * SKK * SATD];
__device__ float g_Q [BB * SQ  * HIDN];
__device__ float g_K [BB * SKK * HIDN];
__device__ float g_V [BB * SKK * HIDN];
__device__ float g_T1[BB * SQ  * HIDN];
__device__ float g_GC[BB * SQ  * HIDN];
__device__ float g_gate[BB * SQ];
__device__ float g_loss[2];

// ---------------- tf32 helpers ----------------
__device__ __forceinline__ unsigned f2tf(float f) {
    unsigned u;
    asm("cvt.rna.tf32.f32 %0, %1;" : "=r"(u) : "f"(f));
    return u;
}
__device__ __forceinline__ float rtf(float f) {
    unsigned u;
    asm("cvt.rna.tf32.f32 %0, %1;" : "=r"(u) : "f"(f));
    return __uint_as_float(u);
}
__device__ __forceinline__ void mma_tf32(float c[4],
                                         unsigned a0, unsigned a1, unsigned a2, unsigned a3,
                                         unsigned b0, unsigned b1)
{
    asm volatile("mma.sync.aligned.m16n8k8.row.col.f32.tf32.tf32.f32 "
                 "{%0,%1,%2,%3}, {%4,%5,%6,%7}, {%8,%9}, {%0,%1,%2,%3};"
                 : "+f"(c[0]), "+f"(c[1]), "+f"(c[2]), "+f"(c[3])
                 : "r"(a0), "r"(a1), "r"(a2), "r"(a3), "r"(b0), "r"(b1));
}

// ---------------- LayerNorm over SATD=768 ----------------
__global__ void ln_kernel(const float* __restrict__ x, const float* __restrict__ gam,
                          const float* __restrict__ bet, float* __restrict__ y)
{
    int row = blockIdx.x;
    const float* xr = x + (size_t)row * SATD;
    float* yr = y + (size_t)row * SATD;
    int tid = threadIdx.x;
    float v[3];
    float s = 0.f, ss = 0.f;
#pragma unroll
    for (int t = 0; t < 3; t++) {
        v[t] = xr[tid + t * 256];
        s += v[t]; ss += v[t] * v[t];
    }
#pragma unroll
    for (int o = 16; o > 0; o >>= 1) {
        s  += __shfl_xor_sync(0xffffffffu, s,  o);
        ss += __shfl_xor_sync(0xffffffffu, ss, o);
    }
    __shared__ float sw[8], ssw[8];
    int w = tid >> 5, lane = tid & 31;
    if (lane == 0) { sw[w] = s; ssw[w] = ss; }
    __syncthreads();
    s = 0.f; ss = 0.f;
#pragma unroll
    for (int i = 0; i < 8; i++) { s += sw[i]; ss += ssw[i]; }
    float mean = s * (1.0f / SATD);
    float var  = ss * (1.0f / SATD) - mean * mean;
    float rstd = rsqrtf(var + 1e-5f);
#pragma unroll
    for (int t = 0; t < 3; t++) {
        int i = tid + t * 256;
        yr[i] = (v[t] - mean) * rstd * gam[i] + bet[i];
    }
}

// ---------------- TF32 GEMM: BM=128 BN=64 BK=16, double-buffered ----------------
__global__ void __launch_bounds__(256, 2) gemm_tf32_kernel(
    const float* __restrict__ A, const float* __restrict__ W,
    const float* __restrict__ bias, const float* __restrict__ add,
    float* __restrict__ C, int M, int N, int K, int fuse_add, int round_out)
{
    __shared__ unsigned As[2][16][136];   // [k][m ^ ((k>>2)<<3)]
    __shared__ unsigned Bs[2][16][72];
    int tid = threadIdx.x;
    int lane = tid & 31, wid = tid >> 5;
    int g = lane >> 2, tg = lane & 3;
    int wm = wid >> 2, wn = wid & 3;
    int m0 = blockIdx.y * 128, n0 = blockIdx.x * 64;

    int ar[2], akq[2];
#pragma unroll
    for (int t = 0; t < 2; t++) { int task = tid + t * 256; ar[t] = task >> 2; akq[t] = task & 3; }
    int bk = tid >> 4, bnq = tid & 15;

    float4 apre[2], bpre;
#pragma unroll
    for (int t = 0; t < 2; t++)
        apre[t] = *(const float4*)&A[(size_t)(m0 + ar[t]) * K + akq[t] * 4];
    bpre = *(const float4*)&W[(size_t)bk * N + n0 + bnq * 4];

#pragma unroll
    for (int t = 0; t < 2; t++) {
        int mp = ar[t] ^ (akq[t] << 3);
        As[0][akq[t] * 4 + 0][mp] = f2tf(apre[t].x);
        As[0][akq[t] * 4 + 1][mp] = f2tf(apre[t].y);
        As[0][akq[t] * 4 + 2][mp] = f2tf(apre[t].z);
        As[0][akq[t] * 4 + 3][mp] = f2tf(apre[t].w);
    }
    *(uint4*)&Bs[0][bk][bnq * 4] =
        make_uint4(f2tf(bpre.x), f2tf(bpre.y), f2tf(bpre.z), f2tf(bpre.w));
    __syncthreads();

    float acc[4][2][4];
#pragma unroll
    for (int i = 0; i < 4; i++)
#pragma unroll
        for (int j = 0; j < 2; j++)
#pragma unroll
            for (int q = 0; q < 4; q++) acc[i][j][q] = 0.f;

    int cur = 0;
    for (int k0 = 0; k0 < K; k0 += 16) {
        int more = (k0 + 16 < K);
        if (more) {
#pragma unroll
            for (int t = 0; t < 2; t++)
                apre[t] = *(const float4*)&A[(size_t)(m0 + ar[t]) * K + k0 + 16 + akq[t] * 4];
            bpre = *(const float4*)&W[(size_t)(k0 + 16 + bk) * N + n0 + bnq * 4];
        }
#pragma unroll
        for (int ks = 0; ks < 16; ks += 8) {
            int s0 = ks * 2, s1 = ks * 2 + 8;
            unsigned af[4][4], bf[2][2];
#pragma unroll
            for (int i = 0; i < 4; i++) {
                int m = wm * 64 + i * 16 + g;
                af[i][0] = As[cur][ks + tg][m ^ s0];
                af[i][1] = As[cur][ks + tg][(m + 8) ^ s0];
                af[i][2] = As[cur][ks + 4 + tg][m ^ s1];
                af[i][3] = As[cur][ks + 4 + tg][(m + 8) ^ s1];
            }
#pragma unroll
            for (int j = 0; j < 2; j++) {
                int n = wn * 16 + j * 8 + g;
                bf[j][0] = Bs[cur][ks + tg][n];
                bf[j][1] = Bs[cur][ks + 4 + tg][n];
            }
#pragma unroll
            for (int i = 0; i < 4; i++)
#pragma unroll
                for (int j = 0; j < 2; j++)
                    mma_tf32(acc[i][j], af[i][0], af[i][1], af[i][2], af[i][3],
                             bf[j][0], bf[j][1]);
        }
        if (more) {
            int nxt = cur ^ 1;
#pragma unroll
            for (int t = 0; t < 2; t++) {
                int mp = ar[t] ^ (akq[t] << 3);
                As[nxt][akq[t] * 4 + 0][mp] = f2tf(apre[t].x);
                As[nxt][akq[t] * 4 + 1][mp] = f2tf(apre[t].y);
                As[nxt][akq[t] * 4 + 2][mp] = f2tf(apre[t].z);
                As[nxt][akq[t] * 4 + 3][mp] = f2tf(apre[t].w);
            }
            *(uint4*)&Bs[nxt][bk][bnq * 4] =
                make_uint4(f2tf(bpre.x), f2tf(bpre.y), f2tf(bpre.z), f2tf(bpre.w));
        }
        __syncthreads();
        cur ^= 1;
    }

    // epilogue
#pragma unroll
    for (int i = 0; i < 4; i++) {
        int r0 = m0 + wm * 64 + i * 16 + g;
#pragma unroll
        for (int j = 0; j < 2; j++) {
            int c = n0 + wn * 16 + j * 8 + 2 * tg;
            float2 bv = *(const float2*)&bias[c];
            size_t i0 = (size_t)r0 * N + c;
            size_t i1 = (size_t)(r0 + 8) * N + c;
            float2 o0 = make_float2(acc[i][j][0] + bv.x, acc[i][j][1] + bv.y);
            float2 o1 = make_float2(acc[i][j][2] + bv.x, acc[i][j][3] + bv.y);
            if (fuse_add) {
                float2 a0 = *(const float2*)&add[i0];
                float2 a1 = *(const float2*)&add[i1];
                o0.x += a0.x; o0.y += a0.y; o1.x += a1.x; o1.y += a1.y;
            }
            if (round_out) {
                o0.x = rtf(o0.x); o0.y = rtf(o0.y);
                o1.x = rtf(o1.x); o1.y = rtf(o1.y);
            }
            *(float2*)&C[i0] = o0;
            *(float2*)&C[i1] = o1;
        }
    }
}

// ---------------- RoPE (in-place), scales and rounds output to tf32 ----------------
__global__ void rope_kernel(float* __restrict__ t, const float* __restrict__ xy, float scale)
{
    int row = blockIdx.x;
    int tid = threadIdx.x;          // 0..319
    int head = tid >> 5;
    int j = tid & 31;
    int jj = j & 15;
    float inv = powf(10000.0f, -(float)jj * (1.0f / 16.0f));
    float coord = xy[(size_t)row * 2 + (j >> 4)];
    float ang = coord * inv;
    float sn, cs;
    sincosf(ang, &sn, &cs);
    float* p = t + (size_t)row * HIDN + head * HD;
    float v1 = p[j];
    float v2 = p[j + 32];
    p[j]      = rtf((v1 * cs - v2 * sn) * scale);
    p[j + 32] = rtf((v1 * sn + v2 * cs) * scale);
}

// ---------------- plucker MLP stage 1 ----------------
__global__ void plucker_kernel(const float* __restrict__ P, const float* __restrict__ Wp1,
                               const float* __restrict__ bp1, float* __restrict__ T1)
{
    int row = blockIdx.x;
    __shared__ float p[6];
    if (threadIdx.x < 6) p[threadIdx.x] = P[(size_t)row * 6 + threadIdx.x];
    __syncthreads();
    for (int n = threadIdx.x; n < HIDN; n += blockDim.x) {
        float a = bp1[n];
#pragma unroll
        for (int k = 0; k < 6; k++) a = fmaf(p[k], Wp1[k * HIDN + n], a);
        T1[(size_t)row * HIDN + n] = a / (1.0f + __expf(-a));
    }
}

// ---------------- gate (vmask folded into stored gate) ----------------
__global__ void gate_kernel(const float* __restrict__ gc, const float* __restrict__ gam,
                            const float* __restrict__ bet, const float* __restrict__ Wg,
                            const float* __restrict__ bg, const float* __restrict__ vmask,
                            float* __restrict__ gate, float* __restrict__ lossacc)
{
    int row = blockIdx.x;
    const float* xr = gc + (size_t)row * HIDN;
    int tid = threadIdx.x;
    __shared__ float xs[HIDN];
    __shared__ float sw[8], ssw[8];
    float s = 0.f, ss = 0.f;
    for (int i = tid; i < HIDN; i += 256) {
        float v = xr[i]; xs[i] = v; s += v; ss += v * v;
    }
#pragma unroll
    for (int o = 16; o > 0; o >>= 1) {
        s  += __shfl_xor_sync(0xffffffffu, s,  o);
        ss += __shfl_xor_sync(0xffffffffu, ss, o);
    }
    int w = tid >> 5, lane = tid & 31;
    if (lane == 0) { sw[w] = s; ssw[w] = ss; }
    __syncthreads();
    s = 0.f; ss = 0.f;
#pragma unroll
    for (int i = 0; i < 8; i++) { s += sw[i]; ss += ssw[i]; }
    float mean = s * (1.0f / HIDN);
    float rstd = rsqrtf(ss * (1.0f / HIDN) - mean * mean + 1e-5f);
    float t = 0.f;
    for (int i = tid; i < HIDN; i += 256)
        t += ((xs[i] - mean) * rstd * gam[i] + bet[i]) * Wg[i];
#pragma unroll
    for (int o = 16; o > 0; o >>= 1) t += __shfl_xor_sync(0xffffffffu, t, o);
    __syncthreads();
    if (lane == 0) sw[w] = t;
    __syncthreads();
    if (tid == 0) {
        float tt = 0.f;
#pragma unroll
        for (int i = 0; i < 8; i++) tt += sw[i];
        float gv = 1.0f / (1.0f + __expf(-(tt + bg[0])));
        bool valid = vmask[row] > 0.5f;
        gate[row] = valid ? gv : 0.0f;
        if (!valid) {
            atomicAdd(&lossacc[0], gv);
            atomicAdd(&lossacc[1], 1.0f);
        }
    }
}

// ---------------- flash attention v3: register-resident S/P, warp = 16q x 64k ----
// grid (SQ/128, NH, BB), 256 threads (8 warps, each owns 16 q-rows, full k).
// Q pre-scaled by 0.125 and tf32-rounded; K/V tf32-rounded by producers.
__global__ void __launch_bounds__(256, 2) attn_kernel(
    const float* __restrict__ Q, const float* __restrict__ K,
    const float* __restrict__ V, const float* __restrict__ gate,
    float* __restrict__ out)
{
    extern __shared__ float smn[];
    float* Qs = smn;                           // [128][68]
    float* Ks = Qs + 128 * 68;                 // [64][68]
    float* Vs = Ks + 64 * 68;                  // [64][72]

    int tid = threadIdx.x;
    int lane = tid & 31, wid = tid >> 5;
    int g = lane >> 2, tg = lane & 3;
    int b = blockIdx.z, h = blockIdx.y, q0 = blockIdx.x * 128;

    const float* Qg = Q + ((size_t)(b * SQ + q0)) * HIDN + h * HD;
#pragma unroll
    for (int t = 0; t < 8; t++) {
        int task = tid + t * 256;
        int q = task >> 4, dq = task & 15;
        *(float4*)&Qs[q * 68 + dq * 4] = *(const float4*)(Qg + (size_t)q * HIDN + dq * 4);
    }

    float acc[8][4];
#pragma unroll
    for (int j = 0; j < 8; j++)
#pragma unroll
        for (int q = 0; q < 4; q++) acc[j][q] = 0.f;
    float m0 = -1e30f, m1 = -1e30f, l0 = 0.f, l1 = 0.f;

    int qrow = wid * 16 + g;                   // this thread's first q row (local)
    int srcA = (lane & ~3) | (tg >> 1);        // shuffle sources for P layout fixup
    int srcB = srcA + 2;
    bool odd = (tg & 1);

    for (int kb = 0; kb < SKK; kb += 64) {
        __syncthreads();   // prev readers of Ks/Vs done (iter0: orders Qs fill)
        const float* Kg = K + ((size_t)(b * SKK + kb)) * HIDN + h * HD;
        const float* Vg = V + ((size_t)(b * SKK + kb)) * HIDN + h * HD;
#pragma unroll
        for (int t = 0; t < 4; t++) {
            int task = tid + t * 256;
            int kk = task >> 4, dq = task & 15;
            *(float4*)&Ks[kk * 68 + dq * 4] = *(const float4*)(Kg + (size_t)kk * HIDN + dq * 4);
            *(float4*)&Vs[kk * 72 + dq * 4] = *(const float4*)(Vg + (size_t)kk * HIDN + dq * 4);
        }
        __syncthreads();

        // S = Q @ K^T : per-warp 16q x 64k, all in registers
        float s[8][4];
#pragma unroll
        for (int j = 0; j < 8; j++)
#pragma unroll
            for (int q = 0; q < 4; q++) s[j][q] = 0.f;
#pragma unroll
        for (int d0 = 0; d0 < 64; d0 += 8) {
            unsigned a0 = __float_as_uint(Qs[qrow * 68 + d0 + tg]);
            unsigned a1 = __float_as_uint(Qs[(qrow + 8) * 68 + d0 + tg]);
            unsigned a2 = __float_as_uint(Qs[qrow * 68 + d0 + 4 + tg]);
            unsigned a3 = __float_as_uint(Qs[(qrow + 8) * 68 + d0 + 4 + tg]);
#pragma unroll
            for (int j = 0; j < 8; j++) {
                unsigned b0 = __float_as_uint(Ks[(j * 8 + g) * 68 + d0 + tg]);
                unsigned b1 = __float_as_uint(Ks[(j * 8 + g) * 68 + d0 + 4 + tg]);
                mma_tf32(s[j], a0, a1, a2, a3, b0, b1);
            }
        }

        // warp-local online softmax (rows g and g+8 of this warp's 16)
        float mx0 = -1e30f, mx1 = -1e30f;
#pragma unroll
        for (int j = 0; j < 8; j++) {
            mx0 = fmaxf(mx0, fmaxf(s[j][0], s[j][1]));
            mx1 = fmaxf(mx1, fmaxf(s[j][2], s[j][3]));
        }
        mx0 = fmaxf(mx0, __shfl_xor_sync(0xffffffffu, mx0, 1));
        mx0 = fmaxf(mx0, __shfl_xor_sync(0xffffffffu, mx0, 2));
        mx1 = fmaxf(mx1, __shfl_xor_sync(0xffffffffu, mx1, 1));
        mx1 = fmaxf(mx1, __shfl_xor_sync(0xffffffffu, mx1, 2));
        float mn0 = fmaxf(m0, mx0), mn1 = fmaxf(m1, mx1);
        float al0 = __expf(m0 - mn0), al1 = __expf(m1 - mn1);
        m0 = mn0; m1 = mn1;
        float rs0 = 0.f, rs1 = 0.f;
#pragma unroll
        for (int j = 0; j < 8; j++) {
            s[j][0] = __expf(s[j][0] - mn0); s[j][1] = __expf(s[j][1] - mn0);
            s[j][2] = __expf(s[j][2] - mn1); s[j][3] = __expf(s[j][3] - mn1);
            rs0 += s[j][0] + s[j][1];
            rs1 += s[j][2] + s[j][3];
            s[j][0] = rtf(s[j][0]); s[j][1] = rtf(s[j][1]);
            s[j][2] = rtf(s[j][2]); s[j][3] = rtf(s[j][3]);
        }
        rs0 += __shfl_xor_sync(0xffffffffu, rs0, 1);
        rs0 += __shfl_xor_sync(0xffffffffu, rs0, 2);
        rs1 += __shfl_xor_sync(0xffffffffu, rs1, 1);
        rs1 += __shfl_xor_sync(0xffffffffu, rs1, 2);
        l0 = l0 * al0 + rs0;
        l1 = l1 * al1 + rs1;
#pragma unroll
        for (int j = 0; j < 8; j++) {
            acc[j][0] *= al0; acc[j][1] *= al0;
            acc[j][2] *= al1; acc[j][3] *= al1;
        }

        // O += P @ V : P C-frag (cols 2tg,2tg+1) -> A-frag (cols tg,tg+4) via shfl
#pragma unroll
        for (int j = 0; j < 8; j++) {                // k-block
            float u0 = __shfl_sync(0xffffffffu, s[j][0], srcA);
            float u1 = __shfl_sync(0xffffffffu, s[j][1], srcA);
            float u2 = __shfl_sync(0xffffffffu, s[j][2], srcA);
            float u3 = __shfl_sync(0xffffffffu, s[j][3], srcA);
            float w0 = __shfl_sync(0xffffffffu, s[j][0], srcB);
            float w1 = __shfl_sync(0xffffffffu, s[j][1], srcB);
            float w2 = __shfl_sync(0xffffffffu, s[j][2], srcB);
            float w3 = __shfl_sync(0xffffffffu, s[j][3], srcB);
            unsigned a0 = __float_as_uint(odd ? u1 : u0);
            unsigned a1 = __float_as_uint(odd ? u3 : u2);
            unsigned a2 = __float_as_uint(odd ? w1 : w0);
            unsigned a3 = __float_as_uint(odd ? w3 : w2);
#pragma unroll
            for (int jd = 0; jd < 8; jd++) {
                unsigned b0 = __float_as_uint(Vs[(j * 8 + tg) * 72 + jd * 8 + g]);
                unsigned b1 = __float_as_uint(Vs[(j * 8 + 4 + tg) * 72 + jd * 8 + g]);
                mma_tf32(acc[jd], a0, a1, a2, a3, b0, b1);
            }
        }
    }

    // epilogue: normalize, gate (mask pre-folded), write
    size_t ridx0 = (size_t)b * SQ + q0 + qrow;
    size_t ridx1 = ridx0 + 8;
    float gm0 = gate[ridx0] / l0;
    float gm1 = gate[ridx1] / l1;
#pragma unroll
    for (int jd = 0; jd < 8; jd++) {
        int col = h * HD + jd * 8 + 2 * tg;
        *(float2*)(out + ridx0 * HIDN + col) = make_float2(acc[jd][0] * gm0, acc[jd][1] * gm0);
        *(float2*)(out + ridx1 * HIDN + col) = make_float2(acc[jd][2] * gm1, acc[jd][3] * gm1);
    }
}

__global__ void zero_loss_kernel(float* l) { l[0] = 0.f; l[1] = 0.f; }
__global__ void loss_final_kernel(const float* l, float* o)
{
    o[0] = l[0] / fmaxf(l[1], 1.0f) * 0.05f;
}

// ---------------- launch ----------------
extern "C" void kernel_launch(void* const* d_in, const int* in_sizes, int n_in,
                              void* d_out, int out_size)
{
    (void)in_sizes; (void)n_in;
    const float* hidden = (const float*)d_in[0];
    const float* sat    = (const float*)d_in[1];
    const float* sat_xy = (const float*)d_in[2];
    const float* bev_xy = (const float*)d_in[3];
    const float* plk    = (const float*)d_in[4];
    const float* vmask  = (const float*)d_in[5];
    const float* Wq  = (const float*)d_in[6];
    const float* bq  = (const float*)d_in[7];
    const float* lng = (const float*)d_in[8];
    const float* lnb = (const float*)d_in[9];
    const float* Wk  = (const float*)d_in[10];
    const float* bk  = (const float*)d_in[11];
    const float* Wv  = (const float*)d_in[12];
    const float* bv  = (const float*)d_in[13];
    const float* Wp1 = (const float*)d_in[14];
    const float* bp1 = (const float*)d_in[15];
    const float* Wp2 = (const float*)d_in[16];
    const float* bp2 = (const float*)d_in[17];
    const float* gg  = (const float*)d_in[18];
    const float* gb  = (const float*)d_in[19];
    const float* Wg  = (const float*)d_in[20];
    const float* bg  = (const float*)d_in[21];
    float* out = (float*)d_out;

    float *pSN, *pQ, *pK, *pV, *pT1, *pGC, *pGate, *pLoss;
    cudaGetSymbolAddress((void**)&pSN,   g_SN);
    cudaGetSymbolAddress((void**)&pQ,    g_Q);
    cudaGetSymbolAddress((void**)&pK,    g_K);
    cudaGetSymbolAddress((void**)&pV,    g_V);
    cudaGetSymbolAddress((void**)&pT1,   g_T1);
    cudaGetSymbolAddress((void**)&pGC,   g_GC);
    cudaGetSymbolAddress((void**)&pGate, g_gate);
    cudaGetSymbolAddress((void**)&pLoss, g_loss);

    static cudaStream_t s1 = nullptr, s2 = nullptr, s3 = nullptr;
    static cudaEvent_t e0, eln, e1, e2, e3;
    if (!s1) {
        cudaStreamCreateWithFlags(&s1, cudaStreamNonBlocking);
        cudaStreamCreateWithFlags(&s2, cudaStreamNonBlocking);
        cudaStreamCreateWithFlags(&s3, cudaStreamNonBlocking);
        cudaEventCreateWithFlags(&e0,  cudaEventDisableTiming);
        cudaEventCreateWithFlags(&eln, cudaEventDisableTiming);
        cudaEventCreateWithFlags(&e1,  cudaEventDisableTiming);
        cudaEventCreateWithFlags(&e2,  cudaEventDisableTiming);
        cudaEventCreateWithFlags(&e3,  cudaEventDisableTiming);
    }

    static const int ATTN_SMEM = (128 * 68 + 64 * 68 + 64 * 72) * 4;
    cudaFuncSetAttribute(attn_kernel, cudaFuncAttributeMaxDynamicSharedMemorySize, ATTN_SMEM);

    dim3 gq(HIDN / 64, (BB * SQ) / 128);    // 10 x 128
    dim3 gk(HIDN / 64, (BB * SKK) / 128);   // 10 x 32

    zero_loss_kernel<<<1, 1>>>(pLoss);
    cudaEventRecord(e0, 0);
    cudaStreamWaitEvent(s1, e0, 0);
    cudaStreamWaitEvent(s2, e0, 0);

    // s1: LN -> K gemm -> rope K ; s3 forks after LN for V gemm (rounds output)
    ln_kernel<<<BB * SKK, 256, 0, s1>>>(sat, lng, lnb, pSN);
    cudaEventRecord(eln, s1);
    cudaStreamWaitEvent(s3, eln, 0);
    gemm_tf32_kernel<<<gk, 256, 0, s1>>>(pSN, Wk, bk, nullptr, pK, BB * SKK, HIDN, SATD, 0, 0);
    rope_kernel<<<BB * SKK, 320, 0, s1>>>(pK, sat_xy, 1.0f);
    cudaEventRecord(e1, s1);
    gemm_tf32_kernel<<<gk, 256, 0, s3>>>(pSN, Wv, bv, nullptr, pV, BB * SKK, HIDN, SATD, 0, 1);
    cudaEventRecord(e3, s3);

    // s2: plucker -> PF gemm -> gate
    plucker_kernel<<<BB * SQ, 256, 0, s2>>>(plk, Wp1, bp1, pT1);
    gemm_tf32_kernel<<<gq, 256, 0, s2>>>(pT1, Wp2, bp2, hidden, pGC, BB * SQ, HIDN, HIDN, 1, 0);
    gate_kernel<<<BB * SQ, 256, 0, s2>>>(pGC, gg, gb, Wg, bg, vmask, pGate, pLoss);
    cudaEventRecord(e2, s2);

    // stream 0: Q gemm -> rope Q (scale 1/8 folded in, tf32-rounded)
    gemm_tf32_kernel<<<gq, 256>>>(hidden, Wq, bq, nullptr, pQ, BB * SQ, HIDN, HIDN, 0, 0);
    rope_kernel<<<BB * SQ, 320>>>(pQ, bev_xy, 0.125f);

    cudaStreamWaitEvent(0, e1, 0);
    cudaStreamWaitEvent(0, e3, 0);
    cudaStreamWaitEvent(0, e2, 0);

    dim3 ga(SQ / 128, NH, BB);
    attn_kernel<<<ga, 256, ATTN_SMEM>>>(pQ, pK, pV, pGate, out);

    loss_final_kernel<<<1, 1>>>(pLoss, out + (out_size - 1));
}